// round 14
// baseline (speedup 1.0000x reference)
#include <cuda_runtime.h>
#include <cuda_bf16.h>
#include <cuda_fp16.h>
#include <cstdint>
#include <math.h>

#define B_  4
#define T_  2048
#define C_  1024
#define NH_ 16
#define HD_ 64
#define M_  (B_*T_)   // 8192 rows

// ---- scratch (static __device__ arrays: allocation-free) ----
static __device__ float g_q[B_*NH_*T_*HD_];    // [b][h][t][d] fp32 (GEMM out)
static __device__ float g_k[B_*NH_*T_*HD_];
static __device__ float g_v[B_*NH_*T_*HD_];
static __device__ __half g_qh[B_*NH_*T_*HD_];  // roped+scaled Q hi
static __device__ __half g_ql[B_*NH_*T_*HD_];  // roped+scaled Q lo
static __device__ __half g_kh[B_*NH_*T_*HD_];  // roped K fp16
static __device__ __half g_vh[B_*NH_*T_*HD_];  // V hi
static __device__ __half g_vl[B_*NH_*T_*HD_];  // V lo
static __device__ float g_cos[T_*32];
static __device__ float g_sin[T_*32];
static __device__ __nv_bfloat16 g_ahi[M_*C_];    // x split hi  [m][k]
static __device__ __nv_bfloat16 g_alo[M_*C_];    // x split lo
static __device__ __nv_bfloat16 g_atthi[M_*C_];  // attn out split hi [m][h*64+d]
static __device__ __nv_bfloat16 g_attlo[M_*C_];
static __device__ __nv_bfloat16 g_bhi[3*C_*C_];  // W transposed [N][K] hi
static __device__ __nv_bfloat16 g_blo[3*C_*C_];  // W transposed [N][K] lo

#define SCL_Q (0.125f * 1.4426950408889634f)   // 1/sqrt(64) * log2(e)

// ============================================================
// helpers (baseline PTX only: works on generic compute_103)
// ============================================================
__device__ __forceinline__ uint32_t smem_u32(const void* p) {
    uint32_t a;
    asm("{ .reg .u64 t; cvta.to.shared.u64 t, %1; cvt.u32.u64 %0, t; }"
        : "=r"(a) : "l"(p));
    return a;
}
__device__ __forceinline__ void cpasync16(uint32_t dst, const void* src) {
    asm volatile("cp.async.ca.shared.global [%0], [%1], 16;"
                 :: "r"(dst), "l"(__cvta_generic_to_global(src)));
}
#define CP_COMMIT() asm volatile("cp.async.commit_group;" ::: "memory")
#define CP_WAIT1()  asm volatile("cp.async.wait_group 1;" ::: "memory")
#define CP_WAIT0()  asm volatile("cp.async.wait_group 0;" ::: "memory")

__device__ __forceinline__ void ldsm4(uint32_t* r, uint32_t addr) {
    asm volatile("ldmatrix.sync.aligned.m8n8.x4.shared.b16 {%0,%1,%2,%3}, [%4];"
                 : "=r"(r[0]), "=r"(r[1]), "=r"(r[2]), "=r"(r[3]) : "r"(addr));
}
__device__ __forceinline__ void ldsm2(uint32_t* r, uint32_t addr) {
    asm volatile("ldmatrix.sync.aligned.m8n8.x2.shared.b16 {%0,%1}, [%2];"
                 : "=r"(r[0]), "=r"(r[1]) : "r"(addr));
}
__device__ __forceinline__ void ldsm2t(uint32_t* r, uint32_t addr) {
    asm volatile("ldmatrix.sync.aligned.m8n8.x2.trans.shared.b16 {%0,%1}, [%2];"
                 : "=r"(r[0]), "=r"(r[1]) : "r"(addr));
}
__device__ __forceinline__ void mma_bf16(float* c, const uint32_t* a, const uint32_t* b) {
    asm volatile("mma.sync.aligned.m16n8k16.row.col.f32.bf16.bf16.f32 "
                 "{%0,%1,%2,%3}, {%4,%5,%6,%7}, {%8,%9}, {%0,%1,%2,%3};"
                 : "+f"(c[0]), "+f"(c[1]), "+f"(c[2]), "+f"(c[3])
                 : "r"(a[0]), "r"(a[1]), "r"(a[2]), "r"(a[3]),
                   "r"(b[0]), "r"(b[1]));
}
__device__ __forceinline__ void mma_f16(float* c, const uint32_t* a, const uint32_t* b) {
    asm volatile("mma.sync.aligned.m16n8k16.row.col.f32.f16.f16.f32 "
                 "{%0,%1,%2,%3}, {%4,%5,%6,%7}, {%8,%9}, {%0,%1,%2,%3};"
                 : "+f"(c[0]), "+f"(c[1]), "+f"(c[2]), "+f"(c[3])
                 : "r"(a[0]), "r"(a[1]), "r"(a[2]), "r"(a[3]),
                   "r"(b[0]), "r"(b[1]));
}
__device__ __forceinline__ uint32_t pk2(__nv_bfloat16 a, __nv_bfloat16 b) {
    __nv_bfloat162 t; t.x = a; t.y = b;
    return *reinterpret_cast<uint32_t*>(&t);
}
__device__ __forceinline__ uint32_t pkh2(float a, float b) {
    __half2 t = __floats2half2_rn(a, b);
    return *reinterpret_cast<uint32_t*>(&t);
}

// ============================================================
// RoPE tables (fp64 once -> fp32 tables)
// ============================================================
__global__ void rope_table_kernel()
{
    int idx = blockIdx.x * blockDim.x + threadIdx.x;
    if (idx >= T_ * 32) return;
    int t = idx >> 5, i = idx & 31;
    double inv = pow(10000.0, -(double)i / 32.0);
    double ang = (double)t * inv;
    g_cos[idx] = (float)cos(ang);
    g_sin[idx] = (float)sin(ang);
}

// ============================================================
// QKV post-pass: RoPE (q,k) + fp16 conversion/split for attention
// ============================================================
__global__ __launch_bounds__(256)
void qkvconv_kernel()
{
    int idx = blockIdx.x * blockDim.x + threadIdx.x;
    const int total = B_ * NH_ * T_ * 32;
    if (idx >= total) return;
    const int sel = blockIdx.y;
    const int i   = idx & 31;
    const int bht = idx >> 5;
    const int t   = bht & (T_ - 1);
    const size_t base = (size_t)bht * HD_;

    if (sel == 0) {
        float x1 = g_q[base + i], x2 = g_q[base + i + 32];
        float c = g_cos[t * 32 + i], s = g_sin[t * 32 + i];
        float r1 = (x1 * c - x2 * s) * SCL_Q;
        float r2 = (x1 * s + x2 * c) * SCL_Q;
        __half h1 = __float2half_rn(r1), h2 = __float2half_rn(r2);
        g_qh[base + i]      = h1;
        g_qh[base + i + 32] = h2;
        g_ql[base + i]      = __float2half_rn(r1 - __half2float(h1));
        g_ql[base + i + 32] = __float2half_rn(r2 - __half2float(h2));
    } else if (sel == 1) {
        float x1 = g_k[base + i], x2 = g_k[base + i + 32];
        float c = g_cos[t * 32 + i], s = g_sin[t * 32 + i];
        g_kh[base + i]      = __float2half_rn(x1 * c - x2 * s);
        g_kh[base + i + 32] = __float2half_rn(x1 * s + x2 * c);
    } else {
        float v1 = g_v[base + i], v2 = g_v[base + i + 32];
        __half h1 = __float2half_rn(v1), h2 = __float2half_rn(v2);
        g_vh[base + i]      = h1;
        g_vh[base + i + 32] = h2;
        g_vl[base + i]      = __float2half_rn(v1 - __half2float(h1));
        g_vl[base + i + 32] = __float2half_rn(v2 - __half2float(h2));
    }
}

// ============================================================
// x -> bf16 hi/lo split (row-major [m][k])
// ============================================================
__global__ __launch_bounds__(256)
void xconv_kernel(const float* __restrict__ x)
{
    int idx = blockIdx.x * 256 + threadIdx.x;   // over M_*C_/4
    float4 v = reinterpret_cast<const float4*>(x)[idx];
    __nv_bfloat16 h0 = __float2bfloat16(v.x);
    __nv_bfloat16 h1 = __float2bfloat16(v.y);
    __nv_bfloat16 h2 = __float2bfloat16(v.z);
    __nv_bfloat16 h3 = __float2bfloat16(v.w);
    uint2 hi = make_uint2(pk2(h0, h1), pk2(h2, h3));
    uint2 lo = make_uint2(
        pk2(__float2bfloat16(v.x - __bfloat162float(h0)),
            __float2bfloat16(v.y - __bfloat162float(h1))),
        pk2(__float2bfloat16(v.z - __bfloat162float(h2)),
            __float2bfloat16(v.w - __bfloat162float(h3))));
    reinterpret_cast<uint2*>(g_ahi)[idx] = hi;
    reinterpret_cast<uint2*>(g_alo)[idx] = lo;
}

// ============================================================
// W transpose + bf16 hi/lo split: g_b{hi,lo}[n][k] = split(W[k][n])
// ============================================================
__global__ __launch_bounds__(256)
void wconv_kernel(const float* __restrict__ W, int N)
{
    __shared__ float s[32][33];
    const int kb = blockIdx.y * 32, nb = blockIdx.x * 32;
    const int tx = threadIdx.x, ty = threadIdx.y;   // 32 x 8
#pragma unroll
    for (int j = 0; j < 4; j++)
        s[ty * 4 + j][tx] = W[(kb + ty * 4 + j) * N + nb + tx];
    __syncthreads();
#pragma unroll
    for (int j = 0; j < 4; j++) {
        float v = s[tx][ty * 4 + j];
        __nv_bfloat16 h = __float2bfloat16(v);
        float lo = v - __bfloat162float(h);
        int idx = (nb + ty * 4 + j) * C_ + kb + tx;
        g_bhi[idx] = h;
        g_blo[idx] = __float2bfloat16(lo);
    }
}

// ============================================================
// bf16 mma.sync GEMM (exact R8 config: 128x128, 8 warps 64x32,
//   BK=64, 2-stage cp.async — proven 398/133 us)
// ============================================================
static constexpr int RSB    = 144;
static constexpr int SA_HI  = 0;
static constexpr int SA_LO  = 18432;
static constexpr int SB_HI  = 36864;
static constexpr int SB_LO  = 55296;
static constexpr int STAGE  = 73728;
static constexpr int SMEM_SZ = 2 * STAGE;   // 147456

template<int N, int MODE>
__global__ __launch_bounds__(256)
void mma_gemm_kernel(const float* __restrict__ bias, float* __restrict__ out)
{
    extern __shared__ __align__(128) char smem[];
    const uint32_t sb = smem_u32(smem);
    const int tid = threadIdx.x, lane = tid & 31, wid = tid >> 5;
    const int wm = wid >> 2, wn = wid & 3;
    const int m0 = blockIdx.y * 128, n0 = blockIdx.x * 128;

    const __nv_bfloat16* Ah = (MODE == 0) ? g_ahi : g_atthi;
    const __nv_bfloat16* Al = (MODE == 0) ? g_alo : g_attlo;

    float acc[4][4][4];
#pragma unroll
    for (int a = 0; a < 4; a++)
#pragma unroll
        for (int b = 0; b < 4; b++)
#pragma unroll
            for (int c = 0; c < 4; c++) acc[a][b][c] = 0.f;

    auto prefetch = [&](int chunk) {
        const int st = chunk & 1;
        const int k0 = chunk * 64;
        const uint32_t sbase = sb + st * STAGE;
#pragma unroll
        for (int i = 0; i < 8; i++) {
            int p = tid + i * 256;
            int sel = p >> 10, q = p & 1023;
            int row = q >> 3, ch = q & 7;
            const __nv_bfloat16* src =
                (sel ? Al : Ah) + (size_t)(m0 + row) * C_ + k0 + ch * 8;
            cpasync16(sbase + (sel ? SA_LO : SA_HI) + row * RSB + ch * 16, src);
        }
#pragma unroll
        for (int i = 0; i < 8; i++) {
            int p = tid + i * 256;
            int sel = p >> 10, q = p & 1023;
            int row = q >> 3, ch = q & 7;
            const __nv_bfloat16* src =
                (sel ? g_blo : g_bhi) + (size_t)(n0 + row) * C_ + k0 + ch * 8;
            cpasync16(sbase + (sel ? SB_LO : SB_HI) + row * RSB + ch * 16, src);
        }
        CP_COMMIT();
    };

    prefetch(0);

    const int a_r = lane & 15;
    const int a_c = (lane >> 4) * 8;
    const int b_r = lane & 7;
    const int b_c = ((lane >> 3) & 1) * 8;

    for (int chunk = 0; chunk < 16; chunk++) {
        if (chunk + 1 < 16) { prefetch(chunk + 1); CP_WAIT1(); }
        else                { CP_WAIT0(); }
        __syncthreads();
        const uint32_t sbase = sb + (chunk & 1) * STAGE;
#pragma unroll
        for (int ks = 0; ks < 4; ks++) {
            uint32_t fAh[4][4], fAl[4][4], fBh[4][2], fBl[4][2];
#pragma unroll
            for (int mi = 0; mi < 4; mi++) {
                uint32_t off = (uint32_t)((wm * 64 + mi * 16 + a_r) * RSB
                                          + (ks * 16 + a_c) * 2);
                ldsm4(fAh[mi], sbase + SA_HI + off);
                ldsm4(fAl[mi], sbase + SA_LO + off);
            }
#pragma unroll
            for (int ni = 0; ni < 4; ni++) {
                uint32_t off = (uint32_t)((wn * 32 + ni * 8 + b_r) * RSB
                                          + (ks * 16 + b_c) * 2);
                ldsm2(fBh[ni], sbase + SB_HI + off);
                ldsm2(fBl[ni], sbase + SB_LO + off);
            }
#pragma unroll
            for (int mi = 0; mi < 4; mi++)
#pragma unroll
                for (int ni = 0; ni < 4; ni++) {
                    mma_bf16(acc[mi][ni], fAh[mi], fBh[ni]);
                    mma_bf16(acc[mi][ni], fAh[mi], fBl[ni]);
                    mma_bf16(acc[mi][ni], fAl[mi], fBh[ni]);
                }
        }
        __syncthreads();
    }

    const int g = lane >> 2, j = lane & 3;
#pragma unroll
    for (int mi = 0; mi < 4; mi++)
#pragma unroll
        for (int ni = 0; ni < 4; ni++)
#pragma unroll
            for (int half = 0; half < 2; half++) {
                int m = m0 + wm * 64 + mi * 16 + g + half * 8;
                int n = n0 + wn * 32 + ni * 8 + 2 * j;
                float v0 = acc[mi][ni][half * 2 + 0] + bias[n];
                float v1 = acc[mi][ni][half * 2 + 1] + bias[n + 1];
                if (MODE == 0) {
                    int sec = n >> 10;
                    int w   = n & 1023;
                    int h = w >> 6, d = w & 63;
                    int bb = m >> 11, t = m & (T_ - 1);
                    float* dst = (sec == 0) ? g_q : (sec == 1) ? g_k : g_v;
                    *(float2*)(dst + (((size_t)(bb * NH_ + h) * T_ + t) * HD_ + d))
                        = make_float2(v0, v1);
                } else {
                    *(float2*)(out + (size_t)m * C_ + n) = make_float2(v0, v1);
                }
            }
}

// ============================================================
// Tensor-core flash attention — fp16 operands PRECONVERTED.
//   smem fills are pure 16B (uint4 = 8 halves) copies.
// ============================================================
static constexpr int ARS = 144;                 // padded row bytes (64 fp16 + 8)
static constexpr int AQ_HI = 0;                 // Q staging (reused after)
static constexpr int AQ_LO = 18432;
static constexpr int AK    = 0;                 // K tile (after Q consumed)
static constexpr int AV_HI = 9216;
static constexpr int AV_LO = 18432;

__global__ __launch_bounds__(256)
void attn_mma_kernel()
{
    __shared__ __align__(128) char sm[36864];
    const uint32_t sb = smem_u32(sm);
    const int tid = threadIdx.x, lane = tid & 31, w = tid >> 5;
    const int bh = blockIdx.y;
    const int qt = gridDim.x - 1 - blockIdx.x;     // heavy tiles first
    const int q0 = qt * 128;

    const __half* Qh = g_qh + (size_t)bh * T_ * HD_;
    const __half* Ql = g_ql + (size_t)bh * T_ * HD_;
    const __half* Kh = g_kh + (size_t)bh * T_ * HD_;
    const __half* Vh = g_vh + (size_t)bh * T_ * HD_;
    const __half* Vl = g_vl + (size_t)bh * T_ * HD_;

    // ---- stage Q (precomputed fp16 hi/lo): 128 rows x 8 uint4 ----
#pragma unroll
    for (int i = 0; i < 4; i++) {
        int p = tid + i * 256;          // 0..1023
        int row = p >> 3, c8 = (p & 7) * 8;   // 8 halves = 16B per slot
        uint32_t off = row * ARS + c8 * 2;
        *(uint4*)(sm + AQ_HI + off) =
            *(const uint4*)(Qh + (size_t)(q0 + row) * HD_ + c8);
        *(uint4*)(sm + AQ_LO + off) =
            *(const uint4*)(Ql + (size_t)(q0 + row) * HD_ + c8);
    }
    __syncthreads();

    // ---- Q fragments into registers ----
    const int a_r = lane & 15, a_c = (lane >> 4) * 8;
    uint32_t aQh[4][4], aQl[4][4];
#pragma unroll
    for (int ks = 0; ks < 4; ks++) {
        uint32_t off = (uint32_t)((w * 16 + a_r) * ARS + (ks * 16 + a_c) * 2);
        ldsm4(aQh[ks], sb + AQ_HI + off);
        ldsm4(aQl[ks], sb + AQ_LO + off);
    }
    __syncthreads();   // Q smem region now free for K/V

    float o[8][4];
#pragma unroll
    for (int n = 0; n < 8; n++)
#pragma unroll
        for (int c = 0; c < 4; c++) o[n][c] = 0.f;
    float mrow0 = -INFINITY, mrow1 = -INFINITY;
    float lrow0 = 0.f, lrow1 = 0.f;

    const int g = lane >> 2, j = lane & 3;
    const int b_r = lane & 7, b_c = ((lane >> 3) & 1) * 8;
    const int qw0 = q0 + w * 16;                  // warp's first query row
    const int ntiles = qt * 2 + 2;

    for (int kt = 0; kt < ntiles; kt++) {
        const int k0 = kt * 64;
        // ---- fill K, Vhi, Vlo tiles: 64 rows x 8 uint4 each ----
#pragma unroll
        for (int i = 0; i < 2; i++) {
            int p = tid + i * 256;       // 0..511
            int row = p >> 3, c8 = (p & 7) * 8;
            uint32_t off = row * ARS + c8 * 2;
            const size_t gsrc = (size_t)(k0 + row) * HD_ + c8;
            *(uint4*)(sm + AK + off)    = *(const uint4*)(Kh + gsrc);
            *(uint4*)(sm + AV_HI + off) = *(const uint4*)(Vh + gsrc);
            *(uint4*)(sm + AV_LO + off) = *(const uint4*)(Vl + gsrc);
        }
        __syncthreads();

        if (k0 <= qw0 + 15) {   // warp has at least one unmasked row
            // ---- S = Q . K^T ----
            float c[8][4];
#pragma unroll
            for (int n = 0; n < 8; n++)
#pragma unroll
                for (int cc = 0; cc < 4; cc++) c[n][cc] = 0.f;
#pragma unroll
            for (int ks = 0; ks < 4; ks++) {
#pragma unroll
                for (int nn = 0; nn < 8; nn++) {
                    uint32_t bK[2];
                    ldsm2(bK, sb + AK + (uint32_t)((nn * 8 + b_r) * ARS
                                                   + (ks * 16 + b_c) * 2));
                    mma_f16(c[nn], aQh[ks], bK);
                    mma_f16(c[nn], aQl[ks], bK);
                }
            }
            // ---- causal mask ----
            if (k0 + 63 > qw0) {
                const int r0 = qw0 + g, r1 = qw0 + 8 + g;
#pragma unroll
                for (int nn = 0; nn < 8; nn++) {
                    int key = k0 + nn * 8 + 2 * j;
                    if (key     > r0) c[nn][0] = -INFINITY;
                    if (key + 1 > r0) c[nn][1] = -INFINITY;
                    if (key     > r1) c[nn][2] = -INFINITY;
                    if (key + 1 > r1) c[nn][3] = -INFINITY;
                }
            }
            // ---- row max (reduce over j lanes) ----
            float t0 = -INFINITY, t1 = -INFINITY;
#pragma unroll
            for (int nn = 0; nn < 8; nn++) {
                t0 = fmaxf(t0, fmaxf(c[nn][0], c[nn][1]));
                t1 = fmaxf(t1, fmaxf(c[nn][2], c[nn][3]));
            }
            t0 = fmaxf(t0, __shfl_xor_sync(0xffffffffu, t0, 1));
            t0 = fmaxf(t0, __shfl_xor_sync(0xffffffffu, t0, 2));
            t1 = fmaxf(t1, __shfl_xor_sync(0xffffffffu, t1, 1));
            t1 = fmaxf(t1, __shfl_xor_sync(0xffffffffu, t1, 2));
            float mn0 = fmaxf(mrow0, t0), mn1 = fmaxf(mrow1, t1);
            float al0 = exp2f(mrow0 - mn0), al1 = exp2f(mrow1 - mn1);
            mrow0 = mn0; mrow1 = mn1;
            lrow0 *= al0; lrow1 *= al1;
#pragma unroll
            for (int nn = 0; nn < 8; nn++) {
                o[nn][0] *= al0; o[nn][1] *= al0;
                o[nn][2] *= al1; o[nn][3] *= al1;
            }
            // ---- p = exp2(s-m), split fp16 hi/lo, build A frags ----
            uint32_t aPh[4][4], aPl[4][4];
#pragma unroll
            for (int nn = 0; nn < 8; nn++) {
                float p0 = exp2f(c[nn][0] - mn0);
                float p1 = exp2f(c[nn][1] - mn0);
                float p2 = exp2f(c[nn][2] - mn1);
                float p3 = exp2f(c[nn][3] - mn1);
                lrow0 += p0 + p1;
                lrow1 += p2 + p3;
                __half2 h01 = __floats2half2_rn(p0, p1);
                __half2 h23 = __floats2half2_rn(p2, p3);
                float2 f01 = __half22float2(h01);
                float2 f23 = __half22float2(h23);
                int ks = nn >> 1, sl = (nn & 1) * 2;
                aPh[ks][sl + 0] = *(uint32_t*)&h01;
                aPh[ks][sl + 1] = *(uint32_t*)&h23;
                aPl[ks][sl + 0] = pkh2(p0 - f01.x, p1 - f01.y);
                aPl[ks][sl + 1] = pkh2(p2 - f23.x, p3 - f23.y);
            }
            // ---- O += P . V ----
#pragma unroll
            for (int ks = 0; ks < 4; ks++) {
                uint32_t rbase = sb + (uint32_t)((ks * 16 + (lane & 15)) * ARS);
#pragma unroll
                for (int nn = 0; nn < 8; nn++) {
                    uint32_t bVh[2], bVl[2];
                    ldsm2t(bVh, rbase + AV_HI + nn * 16);
                    ldsm2t(bVl, rbase + AV_LO + nn * 16);
                    mma_f16(o[nn], aPh[ks], bVh);
                    mma_f16(o[nn], aPl[ks], bVh);
                    mma_f16(o[nn], aPh[ks], bVl);
                }
            }
        }
        __syncthreads();
    }

    // ---- finalize: reduce l over j lanes, normalize, write split ----
    lrow0 += __shfl_xor_sync(0xffffffffu, lrow0, 1);
    lrow0 += __shfl_xor_sync(0xffffffffu, lrow0, 2);
    lrow1 += __shfl_xor_sync(0xffffffffu, lrow1, 1);
    lrow1 += __shfl_xor_sync(0xffffffffu, lrow1, 2);
    float inv0 = 1.f / lrow0, inv1 = 1.f / lrow1;

    const int b = bh >> 4, h = bh & 15;
    const int m0r = q0 + w * 16 + g, m1r = m0r + 8;
    const size_t base0 = (size_t)(b * T_ + m0r) * C_ + h * 64;
    const size_t base1 = (size_t)(b * T_ + m1r) * C_ + h * 64;
#pragma unroll
    for (int nn = 0; nn < 8; nn++) {
        int d = nn * 8 + 2 * j;
        float v0 = o[nn][0] * inv0, v1 = o[nn][1] * inv0;
        float v2 = o[nn][2] * inv1, v3 = o[nn][3] * inv1;
        __nv_bfloat16 h0 = __float2bfloat16(v0), h1 = __float2bfloat16(v1);
        __nv_bfloat16 h2 = __float2bfloat16(v2), h3 = __float2bfloat16(v3);
        *(uint32_t*)(g_atthi + base0 + d) = pk2(h0, h1);
        *(uint32_t*)(g_attlo + base0 + d) =
            pk2(__float2bfloat16(v0 - __bfloat162float(h0)),
                __float2bfloat16(v1 - __bfloat162float(h1)));
        *(uint32_t*)(g_atthi + base1 + d) = pk2(h2, h3);
        *(uint32_t*)(g_attlo + base1 + d) =
            pk2(__float2bfloat16(v2 - __bfloat162float(h2)),
                __float2bfloat16(v3 - __bfloat162float(h3)));
    }
}

// ============================================================
// launcher
// ============================================================
extern "C" void kernel_launch(void* const* d_in, const int* in_sizes, int n_in,
                              void* d_out, int out_size)
{
    (void)in_sizes; (void)n_in;
    const float* x     = (const float*)d_in[0];
    const float* rnn   = (const float*)d_in[1];
    const float* Wqkv  = (const float*)d_in[2];
    const float* bqkv  = (const float*)d_in[3];
    const float* Wproj = (const float*)d_in[4];
    const float* bproj = (const float*)d_in[5];
    float* out = (float*)d_out;

    cudaFuncSetAttribute(mma_gemm_kernel<3 * C_, 0>,
                         cudaFuncAttributeMaxDynamicSharedMemorySize, SMEM_SZ);
    cudaFuncSetAttribute(mma_gemm_kernel<C_, 1>,
                         cudaFuncAttributeMaxDynamicSharedMemorySize, SMEM_SZ);

    rope_table_kernel<<<(T_ * 32 + 255) / 256, 256>>>();

    xconv_kernel<<<M_ * C_ / 4 / 256, 256>>>(x);
    wconv_kernel<<<dim3(3 * C_ / 32, C_ / 32), dim3(32, 8)>>>(Wqkv, 3 * C_);
    mma_gemm_kernel<3 * C_, 0><<<dim3(24, 64), 256, SMEM_SZ>>>(bqkv, nullptr);

    // RoPE + fp16 conversion/split for attention operands
    dim3 cg((B_ * NH_ * T_ * 32 + 255) / 256, 3);
    qkvconv_kernel<<<cg, 256>>>();

    attn_mma_kernel<<<dim3(16, 64), 256>>>();

    wconv_kernel<<<dim3(C_ / 32, C_ / 32), dim3(32, 8)>>>(Wproj, C_);
    mma_gemm_kernel<C_, 1><<<dim3(8, 64), 256, SMEM_SZ>>>(bproj, out);

    if (out_size >= (int)(M_ * C_ + B_ * C_)) {
        cudaMemcpyAsync(out + (size_t)M_ * C_, rnn,
                        (size_t)B_ * C_ * sizeof(float),
                        cudaMemcpyDeviceToDevice);
    }
}

// round 15
// speedup vs baseline: 1.4224x; 1.4224x over previous
#include <cuda_runtime.h>
#include <cuda_bf16.h>
#include <cuda_fp16.h>
#include <cstdint>
#include <math.h>

#define B_  4
#define T_  2048
#define C_  1024
#define NH_ 16
#define HD_ 64
#define M_  (B_*T_)   // 8192 rows

// ---- scratch (static __device__ arrays: allocation-free) ----
static __device__ float g_q[B_*NH_*T_*HD_];    // [b][h][t][d] fp32 (GEMM out)
static __device__ float g_k[B_*NH_*T_*HD_];
static __device__ float g_v[B_*NH_*T_*HD_];
static __device__ __half g_qh[B_*NH_*T_*HD_];  // roped+scaled Q hi
static __device__ __half g_ql[B_*NH_*T_*HD_];  // roped+scaled Q lo
static __device__ __half g_kh[B_*NH_*T_*HD_];  // roped K fp16
static __device__ __half g_vh[B_*NH_*T_*HD_];  // V hi
static __device__ __half g_vl[B_*NH_*T_*HD_];  // V lo
static __device__ float g_cos[T_*32];
static __device__ float g_sin[T_*32];
static __device__ __nv_bfloat16 g_ahi[M_*C_];    // x split hi  [m][k]
static __device__ __nv_bfloat16 g_alo[M_*C_];    // x split lo
static __device__ __nv_bfloat16 g_atthi[M_*C_];  // attn out split hi [m][h*64+d]
static __device__ __nv_bfloat16 g_attlo[M_*C_];
static __device__ __nv_bfloat16 g_bhi[3*C_*C_];  // W transposed [N][K] hi
static __device__ __nv_bfloat16 g_blo[3*C_*C_];  // W transposed [N][K] lo

#define SCL_Q (0.125f * 1.4426950408889634f)   // 1/sqrt(64) * log2(e)

// ============================================================
// helpers (baseline PTX only: works on generic compute_103)
// ============================================================
__device__ __forceinline__ uint32_t smem_u32(const void* p) {
    uint32_t a;
    asm("{ .reg .u64 t; cvta.to.shared.u64 t, %1; cvt.u32.u64 %0, t; }"
        : "=r"(a) : "l"(p));
    return a;
}
__device__ __forceinline__ void cpasync16(uint32_t dst, const void* src) {
    asm volatile("cp.async.ca.shared.global [%0], [%1], 16;"
                 :: "r"(dst), "l"(__cvta_generic_to_global(src)));
}
#define CP_COMMIT() asm volatile("cp.async.commit_group;" ::: "memory")
#define CP_WAIT1()  asm volatile("cp.async.wait_group 1;" ::: "memory")
#define CP_WAIT0()  asm volatile("cp.async.wait_group 0;" ::: "memory")

__device__ __forceinline__ void ldsm4(uint32_t* r, uint32_t addr) {
    asm volatile("ldmatrix.sync.aligned.m8n8.x4.shared.b16 {%0,%1,%2,%3}, [%4];"
                 : "=r"(r[0]), "=r"(r[1]), "=r"(r[2]), "=r"(r[3]) : "r"(addr));
}
__device__ __forceinline__ void ldsm2(uint32_t* r, uint32_t addr) {
    asm volatile("ldmatrix.sync.aligned.m8n8.x2.shared.b16 {%0,%1}, [%2];"
                 : "=r"(r[0]), "=r"(r[1]) : "r"(addr));
}
__device__ __forceinline__ void ldsm2t(uint32_t* r, uint32_t addr) {
    asm volatile("ldmatrix.sync.aligned.m8n8.x2.trans.shared.b16 {%0,%1}, [%2];"
                 : "=r"(r[0]), "=r"(r[1]) : "r"(addr));
}
__device__ __forceinline__ void mma_bf16(float* c, const uint32_t* a, const uint32_t* b) {
    asm volatile("mma.sync.aligned.m16n8k16.row.col.f32.bf16.bf16.f32 "
                 "{%0,%1,%2,%3}, {%4,%5,%6,%7}, {%8,%9}, {%0,%1,%2,%3};"
                 : "+f"(c[0]), "+f"(c[1]), "+f"(c[2]), "+f"(c[3])
                 : "r"(a[0]), "r"(a[1]), "r"(a[2]), "r"(a[3]),
                   "r"(b[0]), "r"(b[1]));
}
__device__ __forceinline__ void mma_f16(float* c, const uint32_t* a, const uint32_t* b) {
    asm volatile("mma.sync.aligned.m16n8k16.row.col.f32.f16.f16.f32 "
                 "{%0,%1,%2,%3}, {%4,%5,%6,%7}, {%8,%9}, {%0,%1,%2,%3};"
                 : "+f"(c[0]), "+f"(c[1]), "+f"(c[2]), "+f"(c[3])
                 : "r"(a[0]), "r"(a[1]), "r"(a[2]), "r"(a[3]),
                   "r"(b[0]), "r"(b[1]));
}
__device__ __forceinline__ uint32_t pk2(__nv_bfloat16 a, __nv_bfloat16 b) {
    __nv_bfloat162 t; t.x = a; t.y = b;
    return *reinterpret_cast<uint32_t*>(&t);
}
__device__ __forceinline__ uint32_t pkh2(float a, float b) {
    __half2 t = __floats2half2_rn(a, b);
    return *reinterpret_cast<uint32_t*>(&t);
}

// ============================================================
// RoPE tables (fp64 once -> fp32 tables)
// ============================================================
__global__ void rope_table_kernel()
{
    int idx = blockIdx.x * blockDim.x + threadIdx.x;
    if (idx >= T_ * 32) return;
    int t = idx >> 5, i = idx & 31;
    double inv = pow(10000.0, -(double)i / 32.0);
    double ang = (double)t * inv;
    g_cos[idx] = (float)cos(ang);
    g_sin[idx] = (float)sin(ang);
}

// ============================================================
// QKV post-pass: RoPE (q,k) + fp16 conversion/split for attention
// ============================================================
__global__ __launch_bounds__(256)
void qkvconv_kernel()
{
    int idx = blockIdx.x * blockDim.x + threadIdx.x;
    const int total = B_ * NH_ * T_ * 32;
    if (idx >= total) return;
    const int sel = blockIdx.y;
    const int i   = idx & 31;
    const int bht = idx >> 5;
    const int t   = bht & (T_ - 1);
    const size_t base = (size_t)bht * HD_;

    if (sel == 0) {
        float x1 = g_q[base + i], x2 = g_q[base + i + 32];
        float c = g_cos[t * 32 + i], s = g_sin[t * 32 + i];
        float r1 = (x1 * c - x2 * s) * SCL_Q;
        float r2 = (x1 * s + x2 * c) * SCL_Q;
        __half h1 = __float2half_rn(r1), h2 = __float2half_rn(r2);
        g_qh[base + i]      = h1;
        g_qh[base + i + 32] = h2;
        g_ql[base + i]      = __float2half_rn(r1 - __half2float(h1));
        g_ql[base + i + 32] = __float2half_rn(r2 - __half2float(h2));
    } else if (sel == 1) {
        float x1 = g_k[base + i], x2 = g_k[base + i + 32];
        float c = g_cos[t * 32 + i], s = g_sin[t * 32 + i];
        g_kh[base + i]      = __float2half_rn(x1 * c - x2 * s);
        g_kh[base + i + 32] = __float2half_rn(x1 * s + x2 * c);
    } else {
        float v1 = g_v[base + i], v2 = g_v[base + i + 32];
        __half h1 = __float2half_rn(v1), h2 = __float2half_rn(v2);
        g_vh[base + i]      = h1;
        g_vh[base + i + 32] = h2;
        g_vl[base + i]      = __float2half_rn(v1 - __half2float(h1));
        g_vl[base + i + 32] = __float2half_rn(v2 - __half2float(h2));
    }
}

// ============================================================
// x -> bf16 hi/lo split (row-major [m][k])
// ============================================================
__global__ __launch_bounds__(256)
void xconv_kernel(const float* __restrict__ x)
{
    int idx = blockIdx.x * 256 + threadIdx.x;   // over M_*C_/4
    float4 v = reinterpret_cast<const float4*>(x)[idx];
    __nv_bfloat16 h0 = __float2bfloat16(v.x);
    __nv_bfloat16 h1 = __float2bfloat16(v.y);
    __nv_bfloat16 h2 = __float2bfloat16(v.z);
    __nv_bfloat16 h3 = __float2bfloat16(v.w);
    uint2 hi = make_uint2(pk2(h0, h1), pk2(h2, h3));
    uint2 lo = make_uint2(
        pk2(__float2bfloat16(v.x - __bfloat162float(h0)),
            __float2bfloat16(v.y - __bfloat162float(h1))),
        pk2(__float2bfloat16(v.z - __bfloat162float(h2)),
            __float2bfloat16(v.w - __bfloat162float(h3))));
    reinterpret_cast<uint2*>(g_ahi)[idx] = hi;
    reinterpret_cast<uint2*>(g_alo)[idx] = lo;
}

// ============================================================
// W transpose + bf16 hi/lo split: g_b{hi,lo}[n][k] = split(W[k][n])
// ============================================================
__global__ __launch_bounds__(256)
void wconv_kernel(const float* __restrict__ W, int N)
{
    __shared__ float s[32][33];
    const int kb = blockIdx.y * 32, nb = blockIdx.x * 32;
    const int tx = threadIdx.x, ty = threadIdx.y;   // 32 x 8
#pragma unroll
    for (int j = 0; j < 4; j++)
        s[ty * 4 + j][tx] = W[(kb + ty * 4 + j) * N + nb + tx];
    __syncthreads();
#pragma unroll
    for (int j = 0; j < 4; j++) {
        float v = s[tx][ty * 4 + j];
        __nv_bfloat16 h = __float2bfloat16(v);
        float lo = v - __bfloat162float(h);
        int idx = (nb + ty * 4 + j) * C_ + kb + tx;
        g_bhi[idx] = h;
        g_blo[idx] = __float2bfloat16(lo);
    }
}

// ============================================================
// bf16 mma.sync GEMM v3: 128x128 block, 8 warps 64x32, BK=32,
//   2-stage cp.async, 80B row stride -> 80KB smem -> 2 CTAs/SM.
//   MODE 0: scatter into g_q/g_k/g_v;  MODE 1: write fp32 out.
// ============================================================
static constexpr int RS3    = 80;             // 32 bf16 = 64B + 16 pad
static constexpr int SA3_HI = 0;              // 128 rows x 80B
static constexpr int SA3_LO = 10240;
static constexpr int SB3_HI = 20480;
static constexpr int SB3_LO = 30720;
static constexpr int STAGE3 = 40960;
static constexpr int SMEM_SZ3 = 2 * STAGE3;   // 81920 -> 2 CTAs/SM

template<int N, int MODE>
__global__ __launch_bounds__(256, 2)
void mma_gemm_kernel(const float* __restrict__ bias, float* __restrict__ out)
{
    extern __shared__ __align__(128) char smem[];
    const uint32_t sb = smem_u32(smem);
    const int tid = threadIdx.x, lane = tid & 31, wid = tid >> 5;
    const int wm = wid >> 2, wn = wid & 3;
    const int m0 = blockIdx.y * 128, n0 = blockIdx.x * 128;

    const __nv_bfloat16* Ah = (MODE == 0) ? g_ahi : g_atthi;
    const __nv_bfloat16* Al = (MODE == 0) ? g_alo : g_attlo;

    float acc[4][4][4];
#pragma unroll
    for (int a = 0; a < 4; a++)
#pragma unroll
        for (int b = 0; b < 4; b++)
#pragma unroll
            for (int c = 0; c < 4; c++) acc[a][b][c] = 0.f;

    auto prefetch = [&](int chunk) {
        const int k0 = chunk * 32;
        const uint32_t sbase = sb + (chunk & 1) * STAGE3;
        // A: 1024 tasks (hi 512 + lo 512); 128 rows x 4 slots of 8 halves
#pragma unroll
        for (int i = 0; i < 4; i++) {
            int p = tid + i * 256;
            int sel = p >> 9, q = p & 511;
            int row = q >> 2, ch = q & 3;
            const __nv_bfloat16* src =
                (sel ? Al : Ah) + (size_t)(m0 + row) * C_ + k0 + ch * 8;
            cpasync16(sbase + (sel ? SA3_LO : SA3_HI) + row * RS3 + ch * 16, src);
        }
        // B: 1024 tasks
#pragma unroll
        for (int i = 0; i < 4; i++) {
            int p = tid + i * 256;
            int sel = p >> 9, q = p & 511;
            int row = q >> 2, ch = q & 3;
            const __nv_bfloat16* src =
                (sel ? g_blo : g_bhi) + (size_t)(n0 + row) * C_ + k0 + ch * 8;
            cpasync16(sbase + (sel ? SB3_LO : SB3_HI) + row * RS3 + ch * 16, src);
        }
        CP_COMMIT();
    };

    prefetch(0);

    const int a_r = lane & 15;
    const int a_c = (lane >> 4) * 8;
    const int b_r = lane & 7;
    const int b_c = ((lane >> 3) & 1) * 8;

    const int NCHUNK = C_ / 32;    // 32
    for (int chunk = 0; chunk < NCHUNK; chunk++) {
        if (chunk + 1 < NCHUNK) { prefetch(chunk + 1); CP_WAIT1(); }
        else                    { CP_WAIT0(); }
        __syncthreads();
        const uint32_t sbase = sb + (chunk & 1) * STAGE3;
#pragma unroll
        for (int ks = 0; ks < 2; ks++) {
            uint32_t fAh[4][4], fAl[4][4], fBh[4][2], fBl[4][2];
#pragma unroll
            for (int mi = 0; mi < 4; mi++) {
                uint32_t off = (uint32_t)((wm * 64 + mi * 16 + a_r) * RS3
                                          + (ks * 16 + a_c) * 2);
                ldsm4(fAh[mi], sbase + SA3_HI + off);
                ldsm4(fAl[mi], sbase + SA3_LO + off);
            }
#pragma unroll
            for (int ni = 0; ni < 4; ni++) {
                uint32_t off = (uint32_t)((wn * 32 + ni * 8 + b_r) * RS3
                                          + (ks * 16 + b_c) * 2);
                ldsm2(fBh[ni], sbase + SB3_HI + off);
                ldsm2(fBl[ni], sbase + SB3_LO + off);
            }
#pragma unroll
            for (int mi = 0; mi < 4; mi++)
#pragma unroll
                for (int ni = 0; ni < 4; ni++) {
                    mma_bf16(acc[mi][ni], fAh[mi], fBh[ni]);
                    mma_bf16(acc[mi][ni], fAh[mi], fBl[ni]);
                    mma_bf16(acc[mi][ni], fAl[mi], fBh[ni]);
                }
        }
        __syncthreads();
    }

    const int g = lane >> 2, j = lane & 3;
#pragma unroll
    for (int mi = 0; mi < 4; mi++)
#pragma unroll
        for (int ni = 0; ni < 4; ni++)
#pragma unroll
            for (int half = 0; half < 2; half++) {
                int m = m0 + wm * 64 + mi * 16 + g + half * 8;
                int n = n0 + wn * 32 + ni * 8 + 2 * j;
                float v0 = acc[mi][ni][half * 2 + 0] + bias[n];
                float v1 = acc[mi][ni][half * 2 + 1] + bias[n + 1];
                if (MODE == 0) {
                    int sec = n >> 10;
                    int w   = n & 1023;
                    int h = w >> 6, d = w & 63;
                    int bb = m >> 11, t = m & (T_ - 1);
                    float* dst = (sec == 0) ? g_q : (sec == 1) ? g_k : g_v;
                    *(float2*)(dst + (((size_t)(bb * NH_ + h) * T_ + t) * HD_ + d))
                        = make_float2(v0, v1);
                } else {
                    *(float2*)(out + (size_t)m * C_ + n) = make_float2(v0, v1);
                }
            }
}

// ============================================================
// Tensor-core flash attention — fp16 operands PRECONVERTED.
//   smem fills are pure 16B (uint4 = 8 halves) copies.
// ============================================================
static constexpr int ARS = 144;                 // padded row bytes (64 fp16 + 8)
static constexpr int AQ_HI = 0;                 // Q staging (reused after)
static constexpr int AQ_LO = 18432;
static constexpr int AK    = 0;                 // K tile (after Q consumed)
static constexpr int AV_HI = 9216;
static constexpr int AV_LO = 18432;

__global__ __launch_bounds__(256)
void attn_mma_kernel()
{
    __shared__ __align__(128) char sm[36864];
    const uint32_t sb = smem_u32(sm);
    const int tid = threadIdx.x, lane = tid & 31, w = tid >> 5;
    const int bh = blockIdx.y;
    const int qt = gridDim.x - 1 - blockIdx.x;     // heavy tiles first
    const int q0 = qt * 128;

    const __half* Qh = g_qh + (size_t)bh * T_ * HD_;
    const __half* Ql = g_ql + (size_t)bh * T_ * HD_;
    const __half* Kh = g_kh + (size_t)bh * T_ * HD_;
    const __half* Vh = g_vh + (size_t)bh * T_ * HD_;
    const __half* Vl = g_vl + (size_t)bh * T_ * HD_;

    // ---- stage Q (precomputed fp16 hi/lo): 128 rows x 8 uint4 ----
#pragma unroll
    for (int i = 0; i < 4; i++) {
        int p = tid + i * 256;          // 0..1023
        int row = p >> 3, c8 = (p & 7) * 8;   // 8 halves = 16B per slot
        uint32_t off = row * ARS + c8 * 2;
        *(uint4*)(sm + AQ_HI + off) =
            *(const uint4*)(Qh + (size_t)(q0 + row) * HD_ + c8);
        *(uint4*)(sm + AQ_LO + off) =
            *(const uint4*)(Ql + (size_t)(q0 + row) * HD_ + c8);
    }
    __syncthreads();

    // ---- Q fragments into registers ----
    const int a_r = lane & 15, a_c = (lane >> 4) * 8;
    uint32_t aQh[4][4], aQl[4][4];
#pragma unroll
    for (int ks = 0; ks < 4; ks++) {
        uint32_t off = (uint32_t)((w * 16 + a_r) * ARS + (ks * 16 + a_c) * 2);
        ldsm4(aQh[ks], sb + AQ_HI + off);
        ldsm4(aQl[ks], sb + AQ_LO + off);
    }
    __syncthreads();   // Q smem region now free for K/V

    float o[8][4];
#pragma unroll
    for (int n = 0; n < 8; n++)
#pragma unroll
        for (int c = 0; c < 4; c++) o[n][c] = 0.f;
    float mrow0 = -INFINITY, mrow1 = -INFINITY;
    float lrow0 = 0.f, lrow1 = 0.f;

    const int g = lane >> 2, j = lane & 3;
    const int b_r = lane & 7, b_c = ((lane >> 3) & 1) * 8;
    const int qw0 = q0 + w * 16;                  // warp's first query row
    const int ntiles = qt * 2 + 2;

    for (int kt = 0; kt < ntiles; kt++) {
        const int k0 = kt * 64;
        // ---- fill K, Vhi, Vlo tiles: 64 rows x 8 uint4 each ----
#pragma unroll
        for (int i = 0; i < 2; i++) {
            int p = tid + i * 256;       // 0..511
            int row = p >> 3, c8 = (p & 7) * 8;
            uint32_t off = row * ARS + c8 * 2;
            const size_t gsrc = (size_t)(k0 + row) * HD_ + c8;
            *(uint4*)(sm + AK + off)    = *(const uint4*)(Kh + gsrc);
            *(uint4*)(sm + AV_HI + off) = *(const uint4*)(Vh + gsrc);
            *(uint4*)(sm + AV_LO + off) = *(const uint4*)(Vl + gsrc);
        }
        __syncthreads();

        if (k0 <= qw0 + 15) {   // warp has at least one unmasked row
            // ---- S = Q . K^T ----
            float c[8][4];
#pragma unroll
            for (int n = 0; n < 8; n++)
#pragma unroll
                for (int cc = 0; cc < 4; cc++) c[n][cc] = 0.f;
#pragma unroll
            for (int ks = 0; ks < 4; ks++) {
#pragma unroll
                for (int nn = 0; nn < 8; nn++) {
                    uint32_t bK[2];
                    ldsm2(bK, sb + AK + (uint32_t)((nn * 8 + b_r) * ARS
                                                   + (ks * 16 + b_c) * 2));
                    mma_f16(c[nn], aQh[ks], bK);
                    mma_f16(c[nn], aQl[ks], bK);
                }
            }
            // ---- causal mask ----
            if (k0 + 63 > qw0) {
                const int r0 = qw0 + g, r1 = qw0 + 8 + g;
#pragma unroll
                for (int nn = 0; nn < 8; nn++) {
                    int key = k0 + nn * 8 + 2 * j;
                    if (key     > r0) c[nn][0] = -INFINITY;
                    if (key + 1 > r0) c[nn][1] = -INFINITY;
                    if (key     > r1) c[nn][2] = -INFINITY;
                    if (key + 1 > r1) c[nn][3] = -INFINITY;
                }
            }
            // ---- row max (reduce over j lanes) ----
            float t0 = -INFINITY, t1 = -INFINITY;
#pragma unroll
            for (int nn = 0; nn < 8; nn++) {
                t0 = fmaxf(t0, fmaxf(c[nn][0], c[nn][1]));
                t1 = fmaxf(t1, fmaxf(c[nn][2], c[nn][3]));
            }
            t0 = fmaxf(t0, __shfl_xor_sync(0xffffffffu, t0, 1));
            t0 = fmaxf(t0, __shfl_xor_sync(0xffffffffu, t0, 2));
            t1 = fmaxf(t1, __shfl_xor_sync(0xffffffffu, t1, 1));
            t1 = fmaxf(t1, __shfl_xor_sync(0xffffffffu, t1, 2));
            float mn0 = fmaxf(mrow0, t0), mn1 = fmaxf(mrow1, t1);
            float al0 = exp2f(mrow0 - mn0), al1 = exp2f(mrow1 - mn1);
            mrow0 = mn0; mrow1 = mn1;
            lrow0 *= al0; lrow1 *= al1;
#pragma unroll
            for (int nn = 0; nn < 8; nn++) {
                o[nn][0] *= al0; o[nn][1] *= al0;
                o[nn][2] *= al1; o[nn][3] *= al1;
            }
            // ---- p = exp2(s-m), split fp16 hi/lo, build A frags ----
            uint32_t aPh[4][4], aPl[4][4];
#pragma unroll
            for (int nn = 0; nn < 8; nn++) {
                float p0 = exp2f(c[nn][0] - mn0);
                float p1 = exp2f(c[nn][1] - mn0);
                float p2 = exp2f(c[nn][2] - mn1);
                float p3 = exp2f(c[nn][3] - mn1);
                lrow0 += p0 + p1;
                lrow1 += p2 + p3;
                __half2 h01 = __floats2half2_rn(p0, p1);
                __half2 h23 = __floats2half2_rn(p2, p3);
                float2 f01 = __half22float2(h01);
                float2 f23 = __half22float2(h23);
                int ks = nn >> 1, sl = (nn & 1) * 2;
                aPh[ks][sl + 0] = *(uint32_t*)&h01;
                aPh[ks][sl + 1] = *(uint32_t*)&h23;
                aPl[ks][sl + 0] = pkh2(p0 - f01.x, p1 - f01.y);
                aPl[ks][sl + 1] = pkh2(p2 - f23.x, p3 - f23.y);
            }
            // ---- O += P . V ----
#pragma unroll
            for (int ks = 0; ks < 4; ks++) {
                uint32_t rbase = sb + (uint32_t)((ks * 16 + (lane & 15)) * ARS);
#pragma unroll
                for (int nn = 0; nn < 8; nn++) {
                    uint32_t bVh[2], bVl[2];
                    ldsm2t(bVh, rbase + AV_HI + nn * 16);
                    ldsm2t(bVl, rbase + AV_LO + nn * 16);
                    mma_f16(o[nn], aPh[ks], bVh);
                    mma_f16(o[nn], aPl[ks], bVh);
                    mma_f16(o[nn], aPh[ks], bVl);
                }
            }
        }
        __syncthreads();
    }

    // ---- finalize: reduce l over j lanes, normalize, write split ----
    lrow0 += __shfl_xor_sync(0xffffffffu, lrow0, 1);
    lrow0 += __shfl_xor_sync(0xffffffffu, lrow0, 2);
    lrow1 += __shfl_xor_sync(0xffffffffu, lrow1, 1);
    lrow1 += __shfl_xor_sync(0xffffffffu, lrow1, 2);
    float inv0 = 1.f / lrow0, inv1 = 1.f / lrow1;

    const int b = bh >> 4, h = bh & 15;
    const int m0r = q0 + w * 16 + g, m1r = m0r + 8;
    const size_t base0 = (size_t)(b * T_ + m0r) * C_ + h * 64;
    const size_t base1 = (size_t)(b * T_ + m1r) * C_ + h * 64;
#pragma unroll
    for (int nn = 0; nn < 8; nn++) {
        int d = nn * 8 + 2 * j;
        float v0 = o[nn][0] * inv0, v1 = o[nn][1] * inv0;
        float v2 = o[nn][2] * inv1, v3 = o[nn][3] * inv1;
        __nv_bfloat16 h0 = __float2bfloat16(v0), h1 = __float2bfloat16(v1);
        __nv_bfloat16 h2 = __float2bfloat16(v2), h3 = __float2bfloat16(v3);
        *(uint32_t*)(g_atthi + base0 + d) = pk2(h0, h1);
        *(uint32_t*)(g_attlo + base0 + d) =
            pk2(__float2bfloat16(v0 - __bfloat162float(h0)),
                __float2bfloat16(v1 - __bfloat162float(h1)));
        *(uint32_t*)(g_atthi + base1 + d) = pk2(h2, h3);
        *(uint32_t*)(g_attlo + base1 + d) =
            pk2(__float2bfloat16(v2 - __bfloat162float(h2)),
                __float2bfloat16(v3 - __bfloat162float(h3)));
    }
}

// ============================================================
// launcher
// ============================================================
extern "C" void kernel_launch(void* const* d_in, const int* in_sizes, int n_in,
                              void* d_out, int out_size)
{
    (void)in_sizes; (void)n_in;
    const float* x     = (const float*)d_in[0];
    const float* rnn   = (const float*)d_in[1];
    const float* Wqkv  = (const float*)d_in[2];
    const float* bqkv  = (const float*)d_in[3];
    const float* Wproj = (const float*)d_in[4];
    const float* bproj = (const float*)d_in[5];
    float* out = (float*)d_out;

    cudaFuncSetAttribute(mma_gemm_kernel<3 * C_, 0>,
                         cudaFuncAttributeMaxDynamicSharedMemorySize, SMEM_SZ3);
    cudaFuncSetAttribute(mma_gemm_kernel<C_, 1>,
                         cudaFuncAttributeMaxDynamicSharedMemorySize, SMEM_SZ3);

    rope_table_kernel<<<(T_ * 32 + 255) / 256, 256>>>();

    xconv_kernel<<<M_ * C_ / 4 / 256, 256>>>(x);
    wconv_kernel<<<dim3(3 * C_ / 32, C_ / 32), dim3(32, 8)>>>(Wqkv, 3 * C_);
    mma_gemm_kernel<3 * C_, 0><<<dim3(24, 64), 256, SMEM_SZ3>>>(bqkv, nullptr);

    // RoPE + fp16 conversion/split for attention operands
    dim3 cg((B_ * NH_ * T_ * 32 + 255) / 256, 3);
    qkvconv_kernel<<<cg, 256>>>();

    attn_mma_kernel<<<dim3(16, 64), 256>>>();

    wconv_kernel<<<dim3(C_ / 32, C_ / 32), dim3(32, 8)>>>(Wproj, C_);
    mma_gemm_kernel<C_, 1><<<dim3(8, 64), 256, SMEM_SZ3>>>(bproj, out);

    if (out_size >= (int)(M_ * C_ + B_ * C_)) {
        cudaMemcpyAsync(out + (size_t)M_ * C_, rnn,
                        (size_t)B_ * C_ * sizeof(float),
                        cudaMemcpyDeviceToDevice);
    }
}

// round 16
// speedup vs baseline: 1.5099x; 1.0615x over previous
#include <cuda_runtime.h>
#include <cuda_bf16.h>
#include <cuda_fp16.h>
#include <cstdint>
#include <math.h>

#define B_  4
#define T_  2048
#define C_  1024
#define NH_ 16
#define HD_ 64
#define M_  (B_*T_)   // 8192 rows

// ---- scratch (static __device__ arrays: allocation-free) ----
static __device__ float g_q[B_*NH_*T_*HD_];    // [b][h][t][d] fp32 (GEMM out)
static __device__ float g_k[B_*NH_*T_*HD_];
static __device__ __half g_qh[B_*NH_*T_*HD_];  // roped+scaled Q hi
static __device__ __half g_ql[B_*NH_*T_*HD_];  // roped+scaled Q lo
static __device__ __half g_kh[B_*NH_*T_*HD_];  // roped K fp16
static __device__ __half g_vh[B_*NH_*T_*HD_];  // V hi (written by GEMM epilogue)
static __device__ __half g_vl[B_*NH_*T_*HD_];  // V lo
static __device__ float g_cos[T_*32];
static __device__ float g_sin[T_*32];
static __device__ __nv_bfloat16 g_ahi[M_*C_];    // x split hi  [m][k]
static __device__ __nv_bfloat16 g_alo[M_*C_];    // x split lo
static __device__ __nv_bfloat16 g_atthi[M_*C_];  // attn out split hi [m][h*64+d]
static __device__ __nv_bfloat16 g_attlo[M_*C_];
static __device__ __nv_bfloat16 g_bhi[3*C_*C_];  // W transposed [N][K] hi
static __device__ __nv_bfloat16 g_blo[3*C_*C_];  // W transposed [N][K] lo

#define SCL_Q (0.125f * 1.4426950408889634f)   // 1/sqrt(64) * log2(e)

// ============================================================
// helpers (baseline PTX only: works on generic compute_103)
// ============================================================
__device__ __forceinline__ uint32_t smem_u32(const void* p) {
    uint32_t a;
    asm("{ .reg .u64 t; cvta.to.shared.u64 t, %1; cvt.u32.u64 %0, t; }"
        : "=r"(a) : "l"(p));
    return a;
}
__device__ __forceinline__ void cpasync16(uint32_t dst, const void* src) {
    asm volatile("cp.async.ca.shared.global [%0], [%1], 16;"
                 :: "r"(dst), "l"(__cvta_generic_to_global(src)));
}
#define CP_COMMIT() asm volatile("cp.async.commit_group;" ::: "memory")
#define CP_WAIT1()  asm volatile("cp.async.wait_group 1;" ::: "memory")
#define CP_WAIT0()  asm volatile("cp.async.wait_group 0;" ::: "memory")

__device__ __forceinline__ void ldsm4(uint32_t* r, uint32_t addr) {
    asm volatile("ldmatrix.sync.aligned.m8n8.x4.shared.b16 {%0,%1,%2,%3}, [%4];"
                 : "=r"(r[0]), "=r"(r[1]), "=r"(r[2]), "=r"(r[3]) : "r"(addr));
}
__device__ __forceinline__ void ldsm2(uint32_t* r, uint32_t addr) {
    asm volatile("ldmatrix.sync.aligned.m8n8.x2.shared.b16 {%0,%1}, [%2];"
                 : "=r"(r[0]), "=r"(r[1]) : "r"(addr));
}
__device__ __forceinline__ void ldsm2t(uint32_t* r, uint32_t addr) {
    asm volatile("ldmatrix.sync.aligned.m8n8.x2.trans.shared.b16 {%0,%1}, [%2];"
                 : "=r"(r[0]), "=r"(r[1]) : "r"(addr));
}
__device__ __forceinline__ void mma_bf16(float* c, const uint32_t* a, const uint32_t* b) {
    asm volatile("mma.sync.aligned.m16n8k16.row.col.f32.bf16.bf16.f32 "
                 "{%0,%1,%2,%3}, {%4,%5,%6,%7}, {%8,%9}, {%0,%1,%2,%3};"
                 : "+f"(c[0]), "+f"(c[1]), "+f"(c[2]), "+f"(c[3])
                 : "r"(a[0]), "r"(a[1]), "r"(a[2]), "r"(a[3]),
                   "r"(b[0]), "r"(b[1]));
}
__device__ __forceinline__ void mma_f16(float* c, const uint32_t* a, const uint32_t* b) {
    asm volatile("mma.sync.aligned.m16n8k16.row.col.f32.f16.f16.f32 "
                 "{%0,%1,%2,%3}, {%4,%5,%6,%7}, {%8,%9}, {%0,%1,%2,%3};"
                 : "+f"(c[0]), "+f"(c[1]), "+f"(c[2]), "+f"(c[3])
                 : "r"(a[0]), "r"(a[1]), "r"(a[2]), "r"(a[3]),
                   "r"(b[0]), "r"(b[1]));
}
__device__ __forceinline__ uint32_t pk2(__nv_bfloat16 a, __nv_bfloat16 b) {
    __nv_bfloat162 t; t.x = a; t.y = b;
    return *reinterpret_cast<uint32_t*>(&t);
}
__device__ __forceinline__ uint32_t pkh2(float a, float b) {
    __half2 t = __floats2half2_rn(a, b);
    return *reinterpret_cast<uint32_t*>(&t);
}

// ============================================================
// RoPE tables (fp64 once -> fp32 tables)
// ============================================================
__global__ void rope_table_kernel()
{
    int idx = blockIdx.x * blockDim.x + threadIdx.x;
    if (idx >= T_ * 32) return;
    int t = idx >> 5, i = idx & 31;
    double inv = pow(10000.0, -(double)i / 32.0);
    double ang = (double)t * inv;
    g_cos[idx] = (float)cos(ang);
    g_sin[idx] = (float)sin(ang);
}

// ============================================================
// QK post-pass: RoPE + fp16 conversion/split (V handled in GEMM epilogue)
// ============================================================
__global__ __launch_bounds__(256)
void qkconv_kernel()
{
    int idx = blockIdx.x * blockDim.x + threadIdx.x;
    const int total = B_ * NH_ * T_ * 32;
    if (idx >= total) return;
    const int sel = blockIdx.y;
    const int i   = idx & 31;
    const int bht = idx >> 5;
    const int t   = bht & (T_ - 1);
    const size_t base = (size_t)bht * HD_;

    if (sel == 0) {
        float x1 = g_q[base + i], x2 = g_q[base + i + 32];
        float c = g_cos[t * 32 + i], s = g_sin[t * 32 + i];
        float r1 = (x1 * c - x2 * s) * SCL_Q;
        float r2 = (x1 * s + x2 * c) * SCL_Q;
        __half h1 = __float2half_rn(r1), h2 = __float2half_rn(r2);
        g_qh[base + i]      = h1;
        g_qh[base + i + 32] = h2;
        g_ql[base + i]      = __float2half_rn(r1 - __half2float(h1));
        g_ql[base + i + 32] = __float2half_rn(r2 - __half2float(h2));
    } else {
        float x1 = g_k[base + i], x2 = g_k[base + i + 32];
        float c = g_cos[t * 32 + i], s = g_sin[t * 32 + i];
        g_kh[base + i]      = __float2half_rn(x1 * c - x2 * s);
        g_kh[base + i + 32] = __float2half_rn(x1 * s + x2 * c);
    }
}

// ============================================================
// x -> bf16 hi/lo split (row-major [m][k])
// ============================================================
__global__ __launch_bounds__(256)
void xconv_kernel(const float* __restrict__ x)
{
    int idx = blockIdx.x * 256 + threadIdx.x;   // over M_*C_/4
    float4 v = reinterpret_cast<const float4*>(x)[idx];
    __nv_bfloat16 h0 = __float2bfloat16(v.x);
    __nv_bfloat16 h1 = __float2bfloat16(v.y);
    __nv_bfloat16 h2 = __float2bfloat16(v.z);
    __nv_bfloat16 h3 = __float2bfloat16(v.w);
    uint2 hi = make_uint2(pk2(h0, h1), pk2(h2, h3));
    uint2 lo = make_uint2(
        pk2(__float2bfloat16(v.x - __bfloat162float(h0)),
            __float2bfloat16(v.y - __bfloat162float(h1))),
        pk2(__float2bfloat16(v.z - __bfloat162float(h2)),
            __float2bfloat16(v.w - __bfloat162float(h3))));
    reinterpret_cast<uint2*>(g_ahi)[idx] = hi;
    reinterpret_cast<uint2*>(g_alo)[idx] = lo;
}

// ============================================================
// W transpose + bf16 hi/lo split: g_b{hi,lo}[n][k] = split(W[k][n])
// ============================================================
__global__ __launch_bounds__(256)
void wconv_kernel(const float* __restrict__ W, int N)
{
    __shared__ float s[32][33];
    const int kb = blockIdx.y * 32, nb = blockIdx.x * 32;
    const int tx = threadIdx.x, ty = threadIdx.y;   // 32 x 8
#pragma unroll
    for (int j = 0; j < 4; j++)
        s[ty * 4 + j][tx] = W[(kb + ty * 4 + j) * N + nb + tx];
    __syncthreads();
#pragma unroll
    for (int j = 0; j < 4; j++) {
        float v = s[tx][ty * 4 + j];
        __nv_bfloat16 h = __float2bfloat16(v);
        float lo = v - __bfloat162float(h);
        int idx = (nb + ty * 4 + j) * C_ + kb + tx;
        g_bhi[idx] = h;
        g_blo[idx] = __float2bfloat16(lo);
    }
}

// ============================================================
// bf16 mma.sync GEMM (exact R8 config: 128x128, 8 warps 64x32,
//   BK=64, 2-stage cp.async, 144B stride — proven 398/133 us)
//   MODE 0: q,k -> fp32 g_q/g_k; v -> fp16 split g_vh/g_vl
//   MODE 1: A := g_atthi/lo, write fp32 out + bias
// ============================================================
static constexpr int RSB    = 144;
static constexpr int SA_HI  = 0;
static constexpr int SA_LO  = 18432;
static constexpr int SB_HI  = 36864;
static constexpr int SB_LO  = 55296;
static constexpr int STAGE  = 73728;
static constexpr int SMEM_SZ = 2 * STAGE;   // 147456

template<int N, int MODE>
__global__ __launch_bounds__(256)
void mma_gemm_kernel(const float* __restrict__ bias, float* __restrict__ out)
{
    extern __shared__ __align__(128) char smem[];
    const uint32_t sb = smem_u32(smem);
    const int tid = threadIdx.x, lane = tid & 31, wid = tid >> 5;
    const int wm = wid >> 2, wn = wid & 3;
    const int m0 = blockIdx.y * 128, n0 = blockIdx.x * 128;

    const __nv_bfloat16* Ah = (MODE == 0) ? g_ahi : g_atthi;
    const __nv_bfloat16* Al = (MODE == 0) ? g_alo : g_attlo;

    float acc[4][4][4];
#pragma unroll
    for (int a = 0; a < 4; a++)
#pragma unroll
        for (int b = 0; b < 4; b++)
#pragma unroll
            for (int c = 0; c < 4; c++) acc[a][b][c] = 0.f;

    auto prefetch = [&](int chunk) {
        const int st = chunk & 1;
        const int k0 = chunk * 64;
        const uint32_t sbase = sb + st * STAGE;
#pragma unroll
        for (int i = 0; i < 8; i++) {
            int p = tid + i * 256;
            int sel = p >> 10, q = p & 1023;
            int row = q >> 3, ch = q & 7;
            const __nv_bfloat16* src =
                (sel ? Al : Ah) + (size_t)(m0 + row) * C_ + k0 + ch * 8;
            cpasync16(sbase + (sel ? SA_LO : SA_HI) + row * RSB + ch * 16, src);
        }
#pragma unroll
        for (int i = 0; i < 8; i++) {
            int p = tid + i * 256;
            int sel = p >> 10, q = p & 1023;
            int row = q >> 3, ch = q & 7;
            const __nv_bfloat16* src =
                (sel ? g_blo : g_bhi) + (size_t)(n0 + row) * C_ + k0 + ch * 8;
            cpasync16(sbase + (sel ? SB_LO : SB_HI) + row * RSB + ch * 16, src);
        }
        CP_COMMIT();
    };

    prefetch(0);

    const int a_r = lane & 15;
    const int a_c = (lane >> 4) * 8;
    const int b_r = lane & 7;
    const int b_c = ((lane >> 3) & 1) * 8;

    for (int chunk = 0; chunk < 16; chunk++) {
        if (chunk + 1 < 16) { prefetch(chunk + 1); CP_WAIT1(); }
        else                { CP_WAIT0(); }
        __syncthreads();
        const uint32_t sbase = sb + (chunk & 1) * STAGE;
#pragma unroll
        for (int ks = 0; ks < 4; ks++) {
            uint32_t fAh[4][4], fAl[4][4], fBh[4][2], fBl[4][2];
#pragma unroll
            for (int mi = 0; mi < 4; mi++) {
                uint32_t off = (uint32_t)((wm * 64 + mi * 16 + a_r) * RSB
                                          + (ks * 16 + a_c) * 2);
                ldsm4(fAh[mi], sbase + SA_HI + off);
                ldsm4(fAl[mi], sbase + SA_LO + off);
            }
#pragma unroll
            for (int ni = 0; ni < 4; ni++) {
                uint32_t off = (uint32_t)((wn * 32 + ni * 8 + b_r) * RSB
                                          + (ks * 16 + b_c) * 2);
                ldsm2(fBh[ni], sbase + SB_HI + off);
                ldsm2(fBl[ni], sbase + SB_LO + off);
            }
#pragma unroll
            for (int mi = 0; mi < 4; mi++)
#pragma unroll
                for (int ni = 0; ni < 4; ni++) {
                    mma_bf16(acc[mi][ni], fAh[mi], fBh[ni]);
                    mma_bf16(acc[mi][ni], fAh[mi], fBl[ni]);
                    mma_bf16(acc[mi][ni], fAl[mi], fBh[ni]);
                }
        }
        __syncthreads();
    }

    const int g = lane >> 2, j = lane & 3;
#pragma unroll
    for (int mi = 0; mi < 4; mi++)
#pragma unroll
        for (int ni = 0; ni < 4; ni++)
#pragma unroll
            for (int half = 0; half < 2; half++) {
                int m = m0 + wm * 64 + mi * 16 + g + half * 8;
                int n = n0 + wn * 32 + ni * 8 + 2 * j;
                float v0 = acc[mi][ni][half * 2 + 0] + bias[n];
                float v1 = acc[mi][ni][half * 2 + 1] + bias[n + 1];
                if (MODE == 0) {
                    int sec = n >> 10;
                    int w   = n & 1023;
                    int h = w >> 6, d = w & 63;
                    int bb = m >> 11, t = m & (T_ - 1);
                    size_t idx = ((size_t)(bb * NH_ + h) * T_ + t) * HD_ + d;
                    if (sec == 2) {
                        // V: fp16 hi/lo split directly (no RoPE)
                        __half h0 = __float2half_rn(v0), h1 = __float2half_rn(v1);
                        __half2 hp; hp.x = h0; hp.y = h1;
                        *(uint32_t*)(g_vh + idx) = *(uint32_t*)&hp;
                        *(uint32_t*)(g_vl + idx) =
                            pkh2(v0 - __half2float(h0), v1 - __half2float(h1));
                    } else {
                        float* dst = (sec == 0) ? g_q : g_k;
                        *(float2*)(dst + idx) = make_float2(v0, v1);
                    }
                } else {
                    *(float2*)(out + (size_t)m * C_ + n) = make_float2(v0, v1);
                }
            }
}

// ============================================================
// Tensor-core flash attention — fp16 operands PRECONVERTED.
//   smem fills are pure 16B (uint4 = 8 halves) copies.
// ============================================================
static constexpr int ARS = 144;                 // padded row bytes (64 fp16 + 8)
static constexpr int AQ_HI = 0;                 // Q staging (reused after)
static constexpr int AQ_LO = 18432;
static constexpr int AK    = 0;                 // K tile (after Q consumed)
static constexpr int AV_HI = 9216;
static constexpr int AV_LO = 18432;

__global__ __launch_bounds__(256)
void attn_mma_kernel()
{
    __shared__ __align__(128) char sm[36864];
    const uint32_t sb = smem_u32(sm);
    const int tid = threadIdx.x, lane = tid & 31, w = tid >> 5;
    const int bh = blockIdx.y;
    const int qt = gridDim.x - 1 - blockIdx.x;     // heavy tiles first
    const int q0 = qt * 128;

    const __half* Qh = g_qh + (size_t)bh * T_ * HD_;
    const __half* Ql = g_ql + (size_t)bh * T_ * HD_;
    const __half* Kh = g_kh + (size_t)bh * T_ * HD_;
    const __half* Vh = g_vh + (size_t)bh * T_ * HD_;
    const __half* Vl = g_vl + (size_t)bh * T_ * HD_;

    // ---- stage Q (precomputed fp16 hi/lo): 128 rows x 8 uint4 ----
#pragma unroll
    for (int i = 0; i < 4; i++) {
        int p = tid + i * 256;          // 0..1023
        int row = p >> 3, c8 = (p & 7) * 8;   // 8 halves = 16B per slot
        uint32_t off = row * ARS + c8 * 2;
        *(uint4*)(sm + AQ_HI + off) =
            *(const uint4*)(Qh + (size_t)(q0 + row) * HD_ + c8);
        *(uint4*)(sm + AQ_LO + off) =
            *(const uint4*)(Ql + (size_t)(q0 + row) * HD_ + c8);
    }
    __syncthreads();

    // ---- Q fragments into registers ----
    const int a_r = lane & 15, a_c = (lane >> 4) * 8;
    uint32_t aQh[4][4], aQl[4][4];
#pragma unroll
    for (int ks = 0; ks < 4; ks++) {
        uint32_t off = (uint32_t)((w * 16 + a_r) * ARS + (ks * 16 + a_c) * 2);
        ldsm4(aQh[ks], sb + AQ_HI + off);
        ldsm4(aQl[ks], sb + AQ_LO + off);
    }
    __syncthreads();   // Q smem region now free for K/V

    float o[8][4];
#pragma unroll
    for (int n = 0; n < 8; n++)
#pragma unroll
        for (int c = 0; c < 4; c++) o[n][c] = 0.f;
    float mrow0 = -INFINITY, mrow1 = -INFINITY;
    float lrow0 = 0.f, lrow1 = 0.f;

    const int g = lane >> 2, j = lane & 3;
    const int b_r = lane & 7, b_c = ((lane >> 3) & 1) * 8;
    const int qw0 = q0 + w * 16;                  // warp's first query row
    const int ntiles = qt * 2 + 2;

    for (int kt = 0; kt < ntiles; kt++) {
        const int k0 = kt * 64;
        // ---- fill K, Vhi, Vlo tiles: 64 rows x 8 uint4 each ----
#pragma unroll
        for (int i = 0; i < 2; i++) {
            int p = tid + i * 256;       // 0..511
            int row = p >> 3, c8 = (p & 7) * 8;
            uint32_t off = row * ARS + c8 * 2;
            const size_t gsrc = (size_t)(k0 + row) * HD_ + c8;
            *(uint4*)(sm + AK + off)    = *(const uint4*)(Kh + gsrc);
            *(uint4*)(sm + AV_HI + off) = *(const uint4*)(Vh + gsrc);
            *(uint4*)(sm + AV_LO + off) = *(const uint4*)(Vl + gsrc);
        }
        __syncthreads();

        if (k0 <= qw0 + 15) {   // warp has at least one unmasked row
            // ---- S = Q . K^T ----
            float c[8][4];
#pragma unroll
            for (int n = 0; n < 8; n++)
#pragma unroll
                for (int cc = 0; cc < 4; cc++) c[n][cc] = 0.f;
#pragma unroll
            for (int ks = 0; ks < 4; ks++) {
#pragma unroll
                for (int nn = 0; nn < 8; nn++) {
                    uint32_t bK[2];
                    ldsm2(bK, sb + AK + (uint32_t)((nn * 8 + b_r) * ARS
                                                   + (ks * 16 + b_c) * 2));
                    mma_f16(c[nn], aQh[ks], bK);
                    mma_f16(c[nn], aQl[ks], bK);
                }
            }
            // ---- causal mask ----
            if (k0 + 63 > qw0) {
                const int r0 = qw0 + g, r1 = qw0 + 8 + g;
#pragma unroll
                for (int nn = 0; nn < 8; nn++) {
                    int key = k0 + nn * 8 + 2 * j;
                    if (key     > r0) c[nn][0] = -INFINITY;
                    if (key + 1 > r0) c[nn][1] = -INFINITY;
                    if (key     > r1) c[nn][2] = -INFINITY;
                    if (key + 1 > r1) c[nn][3] = -INFINITY;
                }
            }
            // ---- row max (reduce over j lanes) ----
            float t0 = -INFINITY, t1 = -INFINITY;
#pragma unroll
            for (int nn = 0; nn < 8; nn++) {
                t0 = fmaxf(t0, fmaxf(c[nn][0], c[nn][1]));
                t1 = fmaxf(t1, fmaxf(c[nn][2], c[nn][3]));
            }
            t0 = fmaxf(t0, __shfl_xor_sync(0xffffffffu, t0, 1));
            t0 = fmaxf(t0, __shfl_xor_sync(0xffffffffu, t0, 2));
            t1 = fmaxf(t1, __shfl_xor_sync(0xffffffffu, t1, 1));
            t1 = fmaxf(t1, __shfl_xor_sync(0xffffffffu, t1, 2));
            float mn0 = fmaxf(mrow0, t0), mn1 = fmaxf(mrow1, t1);
            float al0 = exp2f(mrow0 - mn0), al1 = exp2f(mrow1 - mn1);
            mrow0 = mn0; mrow1 = mn1;
            lrow0 *= al0; lrow1 *= al1;
#pragma unroll
            for (int nn = 0; nn < 8; nn++) {
                o[nn][0] *= al0; o[nn][1] *= al0;
                o[nn][2] *= al1; o[nn][3] *= al1;
            }
            // ---- p = exp2(s-m), split fp16 hi/lo, build A frags ----
            uint32_t aPh[4][4], aPl[4][4];
#pragma unroll
            for (int nn = 0; nn < 8; nn++) {
                float p0 = exp2f(c[nn][0] - mn0);
                float p1 = exp2f(c[nn][1] - mn0);
                float p2 = exp2f(c[nn][2] - mn1);
                float p3 = exp2f(c[nn][3] - mn1);
                lrow0 += p0 + p1;
                lrow1 += p2 + p3;
                __half2 h01 = __floats2half2_rn(p0, p1);
                __half2 h23 = __floats2half2_rn(p2, p3);
                float2 f01 = __half22float2(h01);
                float2 f23 = __half22float2(h23);
                int ks = nn >> 1, sl = (nn & 1) * 2;
                aPh[ks][sl + 0] = *(uint32_t*)&h01;
                aPh[ks][sl + 1] = *(uint32_t*)&h23;
                aPl[ks][sl + 0] = pkh2(p0 - f01.x, p1 - f01.y);
                aPl[ks][sl + 1] = pkh2(p2 - f23.x, p3 - f23.y);
            }
            // ---- O += P . V ----
#pragma unroll
            for (int ks = 0; ks < 4; ks++) {
                uint32_t rbase = sb + (uint32_t)((ks * 16 + (lane & 15)) * ARS);
#pragma unroll
                for (int nn = 0; nn < 8; nn++) {
                    uint32_t bVh[2], bVl[2];
                    ldsm2t(bVh, rbase + AV_HI + nn * 16);
                    ldsm2t(bVl, rbase + AV_LO + nn * 16);
                    mma_f16(o[nn], aPh[ks], bVh);
                    mma_f16(o[nn], aPl[ks], bVh);
                    mma_f16(o[nn], aPh[ks], bVl);
                }
            }
        }
        __syncthreads();
    }

    // ---- finalize: reduce l over j lanes, normalize, write split ----
    lrow0 += __shfl_xor_sync(0xffffffffu, lrow0, 1);
    lrow0 += __shfl_xor_sync(0xffffffffu, lrow0, 2);
    lrow1 += __shfl_xor_sync(0xffffffffu, lrow1, 1);
    lrow1 += __shfl_xor_sync(0xffffffffu, lrow1, 2);
    float inv0 = 1.f / lrow0, inv1 = 1.f / lrow1;

    const int b = bh >> 4, h = bh & 15;
    const int m0r = q0 + w * 16 + g, m1r = m0r + 8;
    const size_t base0 = (size_t)(b * T_ + m0r) * C_ + h * 64;
    const size_t base1 = (size_t)(b * T_ + m1r) * C_ + h * 64;
#pragma unroll
    for (int nn = 0; nn < 8; nn++) {
        int d = nn * 8 + 2 * j;
        float v0 = o[nn][0] * inv0, v1 = o[nn][1] * inv0;
        float v2 = o[nn][2] * inv1, v3 = o[nn][3] * inv1;
        __nv_bfloat16 h0 = __float2bfloat16(v0), h1 = __float2bfloat16(v1);
        __nv_bfloat16 h2 = __float2bfloat16(v2), h3 = __float2bfloat16(v3);
        *(uint32_t*)(g_atthi + base0 + d) = pk2(h0, h1);
        *(uint32_t*)(g_attlo + base0 + d) =
            pk2(__float2bfloat16(v0 - __bfloat162float(h0)),
                __float2bfloat16(v1 - __bfloat162float(h1)));
        *(uint32_t*)(g_atthi + base1 + d) = pk2(h2, h3);
        *(uint32_t*)(g_attlo + base1 + d) =
            pk2(__float2bfloat16(v2 - __bfloat162float(h2)),
                __float2bfloat16(v3 - __bfloat162float(h3)));
    }
}

// ============================================================
// launcher
// ============================================================
extern "C" void kernel_launch(void* const* d_in, const int* in_sizes, int n_in,
                              void* d_out, int out_size)
{
    (void)in_sizes; (void)n_in;
    const float* x     = (const float*)d_in[0];
    const float* rnn   = (const float*)d_in[1];
    const float* Wqkv  = (const float*)d_in[2];
    const float* bqkv  = (const float*)d_in[3];
    const float* Wproj = (const float*)d_in[4];
    const float* bproj = (const float*)d_in[5];
    float* out = (float*)d_out;

    cudaFuncSetAttribute(mma_gemm_kernel<3 * C_, 0>,
                         cudaFuncAttributeMaxDynamicSharedMemorySize, SMEM_SZ);
    cudaFuncSetAttribute(mma_gemm_kernel<C_, 1>,
                         cudaFuncAttributeMaxDynamicSharedMemorySize, SMEM_SZ);

    rope_table_kernel<<<(T_ * 32 + 255) / 256, 256>>>();

    xconv_kernel<<<M_ * C_ / 4 / 256, 256>>>(x);
    wconv_kernel<<<dim3(3 * C_ / 32, C_ / 32), dim3(32, 8)>>>(Wqkv, 3 * C_);
    mma_gemm_kernel<3 * C_, 0><<<dim3(24, 64), 256, SMEM_SZ>>>(bqkv, nullptr);

    // RoPE + fp16 conversion/split for q,k (v done in GEMM epilogue)
    dim3 cg((B_ * NH_ * T_ * 32 + 255) / 256, 2);
    qkconv_kernel<<<cg, 256>>>();

    attn_mma_kernel<<<dim3(16, 64), 256>>>();

    wconv_kernel<<<dim3(C_ / 32, C_ / 32), dim3(32, 8)>>>(Wproj, C_);
    mma_gemm_kernel<C_, 1><<<dim3(8, 64), 256, SMEM_SZ>>>(bproj, out);

    if (out_size >= (int)(M_ * C_ + B_ * C_)) {
        cudaMemcpyAsync(out + (size_t)M_ * C_, rnn,
                        (size_t)B_ * C_ * sizeof(float),
                        cudaMemcpyDeviceToDevice);
    }
}

// round 17
// speedup vs baseline: 1.7975x; 1.1905x over previous
#include <cuda_runtime.h>
#include <cuda_bf16.h>
#include <cuda_fp16.h>
#include <cstdint>
#include <math.h>

#define B_  4
#define T_  2048
#define C_  1024
#define NH_ 16
#define HD_ 64
#define M_  (B_*T_)   // 8192 rows

// ---- scratch (static __device__ arrays: allocation-free) ----
static __device__ float g_q[B_*NH_*T_*HD_];    // [b][h][t][d] fp32 (GEMM out)
static __device__ float g_k[B_*NH_*T_*HD_];
static __device__ __half g_qh[B_*NH_*T_*HD_];  // roped+scaled Q hi
static __device__ __half g_ql[B_*NH_*T_*HD_];  // roped+scaled Q lo
static __device__ __half g_kh[B_*NH_*T_*HD_];  // roped K fp16
static __device__ __half g_vh[B_*NH_*T_*HD_];  // V hi (written by GEMM epilogue)
static __device__ __half g_vl[B_*NH_*T_*HD_];  // V lo
static __device__ float g_cos[T_*32];
static __device__ float g_sin[T_*32];
static __device__ __half g_ahi[M_*C_];    // x split hi  [m][k] (fp16)
static __device__ __half g_alo[M_*C_];    // x split lo
static __device__ __half g_atthi[M_*C_];  // attn out split hi [m][h*64+d]
static __device__ __half g_attlo[M_*C_];
static __device__ __half g_bw[3*C_*C_];   // W transposed [N][K] single fp16

#define SCL_Q (0.125f * 1.4426950408889634f)   // 1/sqrt(64) * log2(e)

// ============================================================
// helpers (baseline PTX only: works on generic compute_103)
// ============================================================
__device__ __forceinline__ uint32_t smem_u32(const void* p) {
    uint32_t a;
    asm("{ .reg .u64 t; cvta.to.shared.u64 t, %1; cvt.u32.u64 %0, t; }"
        : "=r"(a) : "l"(p));
    return a;
}
__device__ __forceinline__ void cpasync16(uint32_t dst, const void* src) {
    asm volatile("cp.async.ca.shared.global [%0], [%1], 16;"
                 :: "r"(dst), "l"(__cvta_generic_to_global(src)));
}
#define CP_COMMIT() asm volatile("cp.async.commit_group;" ::: "memory")
#define CP_WAIT1()  asm volatile("cp.async.wait_group 1;" ::: "memory")
#define CP_WAIT0()  asm volatile("cp.async.wait_group 0;" ::: "memory")

__device__ __forceinline__ void ldsm4(uint32_t* r, uint32_t addr) {
    asm volatile("ldmatrix.sync.aligned.m8n8.x4.shared.b16 {%0,%1,%2,%3}, [%4];"
                 : "=r"(r[0]), "=r"(r[1]), "=r"(r[2]), "=r"(r[3]) : "r"(addr));
}
__device__ __forceinline__ void ldsm2(uint32_t* r, uint32_t addr) {
    asm volatile("ldmatrix.sync.aligned.m8n8.x2.shared.b16 {%0,%1}, [%2];"
                 : "=r"(r[0]), "=r"(r[1]) : "r"(addr));
}
__device__ __forceinline__ void ldsm2t(uint32_t* r, uint32_t addr) {
    asm volatile("ldmatrix.sync.aligned.m8n8.x2.trans.shared.b16 {%0,%1}, [%2];"
                 : "=r"(r[0]), "=r"(r[1]) : "r"(addr));
}
__device__ __forceinline__ void mma_f16(float* c, const uint32_t* a, const uint32_t* b) {
    asm volatile("mma.sync.aligned.m16n8k16.row.col.f32.f16.f16.f32 "
                 "{%0,%1,%2,%3}, {%4,%5,%6,%7}, {%8,%9}, {%0,%1,%2,%3};"
                 : "+f"(c[0]), "+f"(c[1]), "+f"(c[2]), "+f"(c[3])
                 : "r"(a[0]), "r"(a[1]), "r"(a[2]), "r"(a[3]),
                   "r"(b[0]), "r"(b[1]));
}
__device__ __forceinline__ uint32_t pkh2(float a, float b) {
    __half2 t = __floats2half2_rn(a, b);
    return *reinterpret_cast<uint32_t*>(&t);
}

// ============================================================
// RoPE tables (fp64 once -> fp32 tables)
// ============================================================
__global__ void rope_table_kernel()
{
    int idx = blockIdx.x * blockDim.x + threadIdx.x;
    if (idx >= T_ * 32) return;
    int t = idx >> 5, i = idx & 31;
    double inv = pow(10000.0, -(double)i / 32.0);
    double ang = (double)t * inv;
    g_cos[idx] = (float)cos(ang);
    g_sin[idx] = (float)sin(ang);
}

// ============================================================
// QK post-pass: RoPE + fp16 conversion/split (V handled in GEMM epilogue)
// ============================================================
__global__ __launch_bounds__(256)
void qkconv_kernel()
{
    int idx = blockIdx.x * blockDim.x + threadIdx.x;
    const int total = B_ * NH_ * T_ * 32;
    if (idx >= total) return;
    const int sel = blockIdx.y;
    const int i   = idx & 31;
    const int bht = idx >> 5;
    const int t   = bht & (T_ - 1);
    const size_t base = (size_t)bht * HD_;

    if (sel == 0) {
        float x1 = g_q[base + i], x2 = g_q[base + i + 32];
        float c = g_cos[t * 32 + i], s = g_sin[t * 32 + i];
        float r1 = (x1 * c - x2 * s) * SCL_Q;
        float r2 = (x1 * s + x2 * c) * SCL_Q;
        __half h1 = __float2half_rn(r1), h2 = __float2half_rn(r2);
        g_qh[base + i]      = h1;
        g_qh[base + i + 32] = h2;
        g_ql[base + i]      = __float2half_rn(r1 - __half2float(h1));
        g_ql[base + i + 32] = __float2half_rn(r2 - __half2float(h2));
    } else {
        float x1 = g_k[base + i], x2 = g_k[base + i + 32];
        float c = g_cos[t * 32 + i], s = g_sin[t * 32 + i];
        g_kh[base + i]      = __float2half_rn(x1 * c - x2 * s);
        g_kh[base + i + 32] = __float2half_rn(x1 * s + x2 * c);
    }
}

// ============================================================
// x -> fp16 hi/lo split (row-major [m][k])
// ============================================================
__global__ __launch_bounds__(256)
void xconv_kernel(const float* __restrict__ x)
{
    int idx = blockIdx.x * 256 + threadIdx.x;   // over M_*C_/4
    float4 v = reinterpret_cast<const float4*>(x)[idx];
    __half2 h01 = __floats2half2_rn(v.x, v.y);
    __half2 h23 = __floats2half2_rn(v.z, v.w);
    float2 f01 = __half22float2(h01);
    float2 f23 = __half22float2(h23);
    uint2 hi = make_uint2(*(uint32_t*)&h01, *(uint32_t*)&h23);
    uint2 lo = make_uint2(pkh2(v.x - f01.x, v.y - f01.y),
                          pkh2(v.z - f23.x, v.w - f23.y));
    reinterpret_cast<uint2*>(g_ahi)[idx] = hi;
    reinterpret_cast<uint2*>(g_alo)[idx] = lo;
}

// ============================================================
// W transpose + single fp16: g_bw[n][k] = fp16(W[k][n])
// ============================================================
__global__ __launch_bounds__(256)
void wconv_kernel(const float* __restrict__ W, int N)
{
    __shared__ float s[32][33];
    const int kb = blockIdx.y * 32, nb = blockIdx.x * 32;
    const int tx = threadIdx.x, ty = threadIdx.y;   // 32 x 8
#pragma unroll
    for (int j = 0; j < 4; j++)
        s[ty * 4 + j][tx] = W[(kb + ty * 4 + j) * N + nb + tx];
    __syncthreads();
#pragma unroll
    for (int j = 0; j < 4; j++) {
        float v = s[tx][ty * 4 + j];
        int idx = (nb + ty * 4 + j) * C_ + kb + tx;
        g_bw[idx] = __float2half_rn(v);
    }
}

// ============================================================
// fp16 mma.sync GEMM: 128x128 block, 8 warps 64x32, BK=64,
//   2-stage cp.async, 144B stride. 2-product split:
//   D = Ah*B + Al*B  (A fp16 hi/lo, B single fp16)
//   MODE 0: q,k -> fp32 g_q/g_k; v -> fp16 split g_vh/g_vl
//   MODE 1: A := g_atthi/lo, write fp32 out + bias
// ============================================================
static constexpr int RSB    = 144;
static constexpr int SA_HI  = 0;
static constexpr int SA_LO  = 18432;
static constexpr int SB_W   = 36864;
static constexpr int STAGE  = 55296;
static constexpr int SMEM_SZ = 2 * STAGE;   // 110592

template<int N, int MODE>
__global__ __launch_bounds__(256)
void mma_gemm_kernel(const float* __restrict__ bias, float* __restrict__ out)
{
    extern __shared__ __align__(128) char smem[];
    const uint32_t sb = smem_u32(smem);
    const int tid = threadIdx.x, lane = tid & 31, wid = tid >> 5;
    const int wm = wid >> 2, wn = wid & 3;
    const int m0 = blockIdx.y * 128, n0 = blockIdx.x * 128;

    const __half* Ah = (MODE == 0) ? g_ahi : g_atthi;
    const __half* Al = (MODE == 0) ? g_alo : g_attlo;

    float acc[4][4][4];
#pragma unroll
    for (int a = 0; a < 4; a++)
#pragma unroll
        for (int b = 0; b < 4; b++)
#pragma unroll
            for (int c = 0; c < 4; c++) acc[a][b][c] = 0.f;

    auto prefetch = [&](int chunk) {
        const int st = chunk & 1;
        const int k0 = chunk * 64;
        const uint32_t sbase = sb + st * STAGE;
        // A hi+lo: 2048 16B tasks
#pragma unroll
        for (int i = 0; i < 8; i++) {
            int p = tid + i * 256;
            int sel = p >> 10, q = p & 1023;
            int row = q >> 3, ch = q & 7;
            const __half* src =
                (sel ? Al : Ah) + (size_t)(m0 + row) * C_ + k0 + ch * 8;
            cpasync16(sbase + (sel ? SA_LO : SA_HI) + row * RSB + ch * 16, src);
        }
        // B single: 1024 16B tasks
#pragma unroll
        for (int i = 0; i < 4; i++) {
            int p = tid + i * 256;
            int row = p >> 3, ch = p & 7;
            const __half* src =
                g_bw + (size_t)(n0 + row) * C_ + k0 + ch * 8;
            cpasync16(sbase + SB_W + row * RSB + ch * 16, src);
        }
        CP_COMMIT();
    };

    prefetch(0);

    const int a_r = lane & 15;
    const int a_c = (lane >> 4) * 8;
    const int b_r = lane & 7;
    const int b_c = ((lane >> 3) & 1) * 8;

    for (int chunk = 0; chunk < 16; chunk++) {
        if (chunk + 1 < 16) { prefetch(chunk + 1); CP_WAIT1(); }
        else                { CP_WAIT0(); }
        __syncthreads();
        const uint32_t sbase = sb + (chunk & 1) * STAGE;
#pragma unroll
        for (int ks = 0; ks < 4; ks++) {
            uint32_t fAh[4][4], fAl[4][4], fB[4][2];
#pragma unroll
            for (int mi = 0; mi < 4; mi++) {
                uint32_t off = (uint32_t)((wm * 64 + mi * 16 + a_r) * RSB
                                          + (ks * 16 + a_c) * 2);
                ldsm4(fAh[mi], sbase + SA_HI + off);
                ldsm4(fAl[mi], sbase + SA_LO + off);
            }
#pragma unroll
            for (int ni = 0; ni < 4; ni++) {
                uint32_t off = (uint32_t)((wn * 32 + ni * 8 + b_r) * RSB
                                          + (ks * 16 + b_c) * 2);
                ldsm2(fB[ni], sbase + SB_W + off);
            }
#pragma unroll
            for (int mi = 0; mi < 4; mi++)
#pragma unroll
                for (int ni = 0; ni < 4; ni++) {
                    mma_f16(acc[mi][ni], fAh[mi], fB[ni]);
                    mma_f16(acc[mi][ni], fAl[mi], fB[ni]);
                }
        }
        __syncthreads();
    }

    const int g = lane >> 2, j = lane & 3;
#pragma unroll
    for (int mi = 0; mi < 4; mi++)
#pragma unroll
        for (int ni = 0; ni < 4; ni++)
#pragma unroll
            for (int half = 0; half < 2; half++) {
                int m = m0 + wm * 64 + mi * 16 + g + half * 8;
                int n = n0 + wn * 32 + ni * 8 + 2 * j;
                float v0 = acc[mi][ni][half * 2 + 0] + bias[n];
                float v1 = acc[mi][ni][half * 2 + 1] + bias[n + 1];
                if (MODE == 0) {
                    int sec = n >> 10;
                    int w   = n & 1023;
                    int h = w >> 6, d = w & 63;
                    int bb = m >> 11, t = m & (T_ - 1);
                    size_t idx = ((size_t)(bb * NH_ + h) * T_ + t) * HD_ + d;
                    if (sec == 2) {
                        __half h0 = __float2half_rn(v0), h1 = __float2half_rn(v1);
                        __half2 hp; hp.x = h0; hp.y = h1;
                        *(uint32_t*)(g_vh + idx) = *(uint32_t*)&hp;
                        *(uint32_t*)(g_vl + idx) =
                            pkh2(v0 - __half2float(h0), v1 - __half2float(h1));
                    } else {
                        float* dst = (sec == 0) ? g_q : g_k;
                        *(float2*)(dst + idx) = make_float2(v0, v1);
                    }
                } else {
                    *(float2*)(out + (size_t)m * C_ + n) = make_float2(v0, v1);
                }
            }
}

// ============================================================
// Tensor-core flash attention — fp16 operands PRECONVERTED.
//   smem fills are pure 16B (uint4 = 8 halves) copies.
// ============================================================
static constexpr int ARS = 144;                 // padded row bytes (64 fp16 + 8)
static constexpr int AQ_HI = 0;                 // Q staging (reused after)
static constexpr int AQ_LO = 18432;
static constexpr int AK    = 0;                 // K tile (after Q consumed)
static constexpr int AV_HI = 9216;
static constexpr int AV_LO = 18432;

__global__ __launch_bounds__(256)
void attn_mma_kernel()
{
    __shared__ __align__(128) char sm[36864];
    const uint32_t sb = smem_u32(sm);
    const int tid = threadIdx.x, lane = tid & 31, w = tid >> 5;
    const int bh = blockIdx.y;
    const int qt = gridDim.x - 1 - blockIdx.x;     // heavy tiles first
    const int q0 = qt * 128;

    const __half* Qh = g_qh + (size_t)bh * T_ * HD_;
    const __half* Ql = g_ql + (size_t)bh * T_ * HD_;
    const __half* Kh = g_kh + (size_t)bh * T_ * HD_;
    const __half* Vh = g_vh + (size_t)bh * T_ * HD_;
    const __half* Vl = g_vl + (size_t)bh * T_ * HD_;

    // ---- stage Q (precomputed fp16 hi/lo): 128 rows x 8 uint4 ----
#pragma unroll
    for (int i = 0; i < 4; i++) {
        int p = tid + i * 256;          // 0..1023
        int row = p >> 3, c8 = (p & 7) * 8;   // 8 halves = 16B per slot
        uint32_t off = row * ARS + c8 * 2;
        *(uint4*)(sm + AQ_HI + off) =
            *(const uint4*)(Qh + (size_t)(q0 + row) * HD_ + c8);
        *(uint4*)(sm + AQ_LO + off) =
            *(const uint4*)(Ql + (size_t)(q0 + row) * HD_ + c8);
    }
    __syncthreads();

    // ---- Q fragments into registers ----
    const int a_r = lane & 15, a_c = (lane >> 4) * 8;
    uint32_t aQh[4][4], aQl[4][4];
#pragma unroll
    for (int ks = 0; ks < 4; ks++) {
        uint32_t off = (uint32_t)((w * 16 + a_r) * ARS + (ks * 16 + a_c) * 2);
        ldsm4(aQh[ks], sb + AQ_HI + off);
        ldsm4(aQl[ks], sb + AQ_LO + off);
    }
    __syncthreads();   // Q smem region now free for K/V

    float o[8][4];
#pragma unroll
    for (int n = 0; n < 8; n++)
#pragma unroll
        for (int c = 0; c < 4; c++) o[n][c] = 0.f;
    float mrow0 = -INFINITY, mrow1 = -INFINITY;
    float lrow0 = 0.f, lrow1 = 0.f;

    const int g = lane >> 2, j = lane & 3;
    const int b_r = lane & 7, b_c = ((lane >> 3) & 1) * 8;
    const int qw0 = q0 + w * 16;                  // warp's first query row
    const int ntiles = qt * 2 + 2;

    for (int kt = 0; kt < ntiles; kt++) {
        const int k0 = kt * 64;
        // ---- fill K, Vhi, Vlo tiles: 64 rows x 8 uint4 each ----
#pragma unroll
        for (int i = 0; i < 2; i++) {
            int p = tid + i * 256;       // 0..511
            int row = p >> 3, c8 = (p & 7) * 8;
            uint32_t off = row * ARS + c8 * 2;
            const size_t gsrc = (size_t)(k0 + row) * HD_ + c8;
            *(uint4*)(sm + AK + off)    = *(const uint4*)(Kh + gsrc);
            *(uint4*)(sm + AV_HI + off) = *(const uint4*)(Vh + gsrc);
            *(uint4*)(sm + AV_LO + off) = *(const uint4*)(Vl + gsrc);
        }
        __syncthreads();

        if (k0 <= qw0 + 15) {   // warp has at least one unmasked row
            // ---- S = Q . K^T ----
            float c[8][4];
#pragma unroll
            for (int n = 0; n < 8; n++)
#pragma unroll
                for (int cc = 0; cc < 4; cc++) c[n][cc] = 0.f;
#pragma unroll
            for (int ks = 0; ks < 4; ks++) {
#pragma unroll
                for (int nn = 0; nn < 8; nn++) {
                    uint32_t bK[2];
                    ldsm2(bK, sb + AK + (uint32_t)((nn * 8 + b_r) * ARS
                                                   + (ks * 16 + b_c) * 2));
                    mma_f16(c[nn], aQh[ks], bK);
                    mma_f16(c[nn], aQl[ks], bK);
                }
            }
            // ---- causal mask ----
            if (k0 + 63 > qw0) {
                const int r0 = qw0 + g, r1 = qw0 + 8 + g;
#pragma unroll
                for (int nn = 0; nn < 8; nn++) {
                    int key = k0 + nn * 8 + 2 * j;
                    if (key     > r0) c[nn][0] = -INFINITY;
                    if (key + 1 > r0) c[nn][1] = -INFINITY;
                    if (key     > r1) c[nn][2] = -INFINITY;
                    if (key + 1 > r1) c[nn][3] = -INFINITY;
                }
            }
            // ---- row max (reduce over j lanes) ----
            float t0 = -INFINITY, t1 = -INFINITY;
#pragma unroll
            for (int nn = 0; nn < 8; nn++) {
                t0 = fmaxf(t0, fmaxf(c[nn][0], c[nn][1]));
                t1 = fmaxf(t1, fmaxf(c[nn][2], c[nn][3]));
            }
            t0 = fmaxf(t0, __shfl_xor_sync(0xffffffffu, t0, 1));
            t0 = fmaxf(t0, __shfl_xor_sync(0xffffffffu, t0, 2));
            t1 = fmaxf(t1, __shfl_xor_sync(0xffffffffu, t1, 1));
            t1 = fmaxf(t1, __shfl_xor_sync(0xffffffffu, t1, 2));
            float mn0 = fmaxf(mrow0, t0), mn1 = fmaxf(mrow1, t1);
            float al0 = exp2f(mrow0 - mn0), al1 = exp2f(mrow1 - mn1);
            mrow0 = mn0; mrow1 = mn1;
            lrow0 *= al0; lrow1 *= al1;
#pragma unroll
            for (int nn = 0; nn < 8; nn++) {
                o[nn][0] *= al0; o[nn][1] *= al0;
                o[nn][2] *= al1; o[nn][3] *= al1;
            }
            // ---- p = exp2(s-m), split fp16 hi/lo, build A frags ----
            uint32_t aPh[4][4], aPl[4][4];
#pragma unroll
            for (int nn = 0; nn < 8; nn++) {
                float p0 = exp2f(c[nn][0] - mn0);
                float p1 = exp2f(c[nn][1] - mn0);
                float p2 = exp2f(c[nn][2] - mn1);
                float p3 = exp2f(c[nn][3] - mn1);
                lrow0 += p0 + p1;
                lrow1 += p2 + p3;
                __half2 h01 = __floats2half2_rn(p0, p1);
                __half2 h23 = __floats2half2_rn(p2, p3);
                float2 f01 = __half22float2(h01);
                float2 f23 = __half22float2(h23);
                int ks = nn >> 1, sl = (nn & 1) * 2;
                aPh[ks][sl + 0] = *(uint32_t*)&h01;
                aPh[ks][sl + 1] = *(uint32_t*)&h23;
                aPl[ks][sl + 0] = pkh2(p0 - f01.x, p1 - f01.y);
                aPl[ks][sl + 1] = pkh2(p2 - f23.x, p3 - f23.y);
            }
            // ---- O += P . V ----
#pragma unroll
            for (int ks = 0; ks < 4; ks++) {
                uint32_t rbase = sb + (uint32_t)((ks * 16 + (lane & 15)) * ARS);
#pragma unroll
                for (int nn = 0; nn < 8; nn++) {
                    uint32_t bVh[2], bVl[2];
                    ldsm2t(bVh, rbase + AV_HI + nn * 16);
                    ldsm2t(bVl, rbase + AV_LO + nn * 16);
                    mma_f16(o[nn], aPh[ks], bVh);
                    mma_f16(o[nn], aPl[ks], bVh);
                    mma_f16(o[nn], aPh[ks], bVl);
                }
            }
        }
        __syncthreads();
    }

    // ---- finalize: reduce l over j lanes, normalize, write fp16 split ----
    lrow0 += __shfl_xor_sync(0xffffffffu, lrow0, 1);
    lrow0 += __shfl_xor_sync(0xffffffffu, lrow0, 2);
    lrow1 += __shfl_xor_sync(0xffffffffu, lrow1, 1);
    lrow1 += __shfl_xor_sync(0xffffffffu, lrow1, 2);
    float inv0 = 1.f / lrow0, inv1 = 1.f / lrow1;

    const int b = bh >> 4, h = bh & 15;
    const int m0r = q0 + w * 16 + g, m1r = m0r + 8;
    const size_t base0 = (size_t)(b * T_ + m0r) * C_ + h * 64;
    const size_t base1 = (size_t)(b * T_ + m1r) * C_ + h * 64;
#pragma unroll
    for (int nn = 0; nn < 8; nn++) {
        int d = nn * 8 + 2 * j;
        float v0 = o[nn][0] * inv0, v1 = o[nn][1] * inv0;
        float v2 = o[nn][2] * inv1, v3 = o[nn][3] * inv1;
        __half h0 = __float2half_rn(v0), h1 = __float2half_rn(v1);
        __half h2 = __float2half_rn(v2), h3 = __float2half_rn(v3);
        __half2 p01; p01.x = h0; p01.y = h1;
        __half2 p23; p23.x = h2; p23.y = h3;
        *(uint32_t*)(g_atthi + base0 + d) = *(uint32_t*)&p01;
        *(uint32_t*)(g_attlo + base0 + d) =
            pkh2(v0 - __half2float(h0), v1 - __half2float(h1));
        *(uint32_t*)(g_atthi + base1 + d) = *(uint32_t*)&p23;
        *(uint32_t*)(g_attlo + base1 + d) =
            pkh2(v2 - __half2float(h2), v3 - __half2float(h3));
    }
}

// ============================================================
// launcher
// ============================================================
extern "C" void kernel_launch(void* const* d_in, const int* in_sizes, int n_in,
                              void* d_out, int out_size)
{
    (void)in_sizes; (void)n_in;
    const float* x     = (const float*)d_in[0];
    const float* rnn   = (const float*)d_in[1];
    const float* Wqkv  = (const float*)d_in[2];
    const float* bqkv  = (const float*)d_in[3];
    const float* Wproj = (const float*)d_in[4];
    const float* bproj = (const float*)d_in[5];
    float* out = (float*)d_out;

    cudaFuncSetAttribute(mma_gemm_kernel<3 * C_, 0>,
                         cudaFuncAttributeMaxDynamicSharedMemorySize, SMEM_SZ);
    cudaFuncSetAttribute(mma_gemm_kernel<C_, 1>,
                         cudaFuncAttributeMaxDynamicSharedMemorySize, SMEM_SZ);

    rope_table_kernel<<<(T_ * 32 + 255) / 256, 256>>>();

    xconv_kernel<<<M_ * C_ / 4 / 256, 256>>>(x);
    wconv_kernel<<<dim3(3 * C_ / 32, C_ / 32), dim3(32, 8)>>>(Wqkv, 3 * C_);
    mma_gemm_kernel<3 * C_, 0><<<dim3(24, 64), 256, SMEM_SZ>>>(bqkv, nullptr);

    // RoPE + fp16 conversion/split for q,k (v done in GEMM epilogue)
    dim3 cg((B_ * NH_ * T_ * 32 + 255) / 256, 2);
    qkconv_kernel<<<cg, 256>>>();

    attn_mma_kernel<<<dim3(16, 64), 256>>>();

    wconv_kernel<<<dim3(C_ / 32, C_ / 32), dim3(32, 8)>>>(Wproj, C_);
    mma_gemm_kernel<C_, 1><<<dim3(8, 64), 256, SMEM_SZ>>>(bproj, out);

    if (out_size >= (int)(M_ * C_ + B_ * C_)) {
        cudaMemcpyAsync(out + (size_t)M_ * C_, rnn,
                        (size_t)B_ * C_ * sizeof(float),
                        cudaMemcpyDeviceToDevice);
    }
}